// round 3
// baseline (speedup 1.0000x reference)
#include <cuda_runtime.h>
#include <cuda_bf16.h>
#include <math.h>
#include <stdint.h>

// ---------------------------------------------------------------------------
// Shapes: x (T=4096, B=2, E=1024); H=16 heads, dk=dv=64; window 512 (513 rel pos)
// QKV matrix rows = t*B + b (8192), cols = h*192 + c  (c<64 q, 64..127 k, 128..191 v)
// ---------------------------------------------------------------------------
#define NROWS 8192
#define EMB   1024
#define QKV_N 3072
#define FFN_I 4096
#define NJ    513

// scratch offsets (floats)
#define OFF_H      0ull
#define OFF_ATTNV  8388608ull
#define OFF_OUT1   16777216ull
#define OFF_H2     25165824ull
#define OFF_QKV    33554432ull   // 8192*3072 = 25165824 -> ends 58720256
#define OFF_FF1    58720256ull   // 8192*4096 = 33554432 -> ends 92274688
#define OFF_QE     92274688ull   // 131072*513 = 67239936 -> ends 159514624
#define SCRATCH_FLOATS 159514624ull

__device__ float g_scratch[SCRATCH_FLOATS];

// ---------------------------------------------------------------------------
// LayerNorm: one block (256 thr) per row of 1024 (float4 per thread)
// ---------------------------------------------------------------------------
__global__ __launch_bounds__(256) void ln_kernel(
    const float* __restrict__ X, const float* __restrict__ G,
    const float* __restrict__ Bt, float* __restrict__ Y)
{
    __shared__ float ssum[8], ssq[8], smv[2];
    int row = blockIdx.x;
    int tid = threadIdx.x;
    const float4* xr = (const float4*)(X + (size_t)row * EMB);
    float4 v = xr[tid];
    float s = v.x + v.y + v.z + v.w;
    float q = v.x*v.x + v.y*v.y + v.z*v.z + v.w*v.w;
#pragma unroll
    for (int o = 16; o > 0; o >>= 1) {
        s += __shfl_xor_sync(0xffffffffu, s, o);
        q += __shfl_xor_sync(0xffffffffu, q, o);
    }
    if ((tid & 31) == 0) { ssum[tid >> 5] = s; ssq[tid >> 5] = q; }
    __syncthreads();
    if (tid == 0) {
        float S = 0.f, Q = 0.f;
#pragma unroll
        for (int i = 0; i < 8; i++) { S += ssum[i]; Q += ssq[i]; }
        float mean = S * (1.f / EMB);
        float var  = Q * (1.f / EMB) - mean * mean;
        smv[0] = mean;
        smv[1] = rsqrtf(var + 1e-5f);
    }
    __syncthreads();
    float mean = smv[0], inv = smv[1];
    float4 g = ((const float4*)G)[tid];
    float4 b = ((const float4*)Bt)[tid];
    float4 o;
    o.x = (v.x - mean) * inv * g.x + b.x;
    o.y = (v.y - mean) * inv * g.y + b.y;
    o.z = (v.z - mean) * inv * g.z + b.z;
    o.w = (v.w - mean) * inv * g.w + b.w;
    ((float4*)(Y + (size_t)row * EMB))[tid] = o;
}

// ---------------------------------------------------------------------------
// SGEMM NT: C[M,N] = A[M,K] * B[N,K]^T (+bias[n]) (relu) (+Res[m,n])
// 128x128 tile, BK=16, 256 threads, 8x8/thread, register prefetch
// ---------------------------------------------------------------------------
template<bool BIAS, bool RELU, bool RES>
__global__ __launch_bounds__(256) void sgemm_nt(
    const float* __restrict__ A, const float* __restrict__ Bw,
    const float* __restrict__ bias, const float* __restrict__ Res,
    float* __restrict__ C, int M, int N, int K)
{
    __shared__ float As[16][132];
    __shared__ float Bs[16][132];
    const int bm = blockIdx.y * 128, bn = blockIdx.x * 128;
    const int tid = threadIdx.x;
    const int lr = tid >> 2;            // 0..63
    const int lc = (tid & 3) << 2;      // 0,4,8,12
    const float* Ap = A  + (size_t)(bm + lr) * K + lc;
    const float* Bp = Bw + (size_t)(bn + lr) * K + lc;
    const size_t stR = (size_t)64 * K;

    float4 pa0 = *(const float4*)Ap;
    float4 pa1 = *(const float4*)(Ap + stR);
    float4 pb0 = *(const float4*)Bp;
    float4 pb1 = *(const float4*)(Bp + stR);

    float acc[8][8];
#pragma unroll
    for (int i = 0; i < 8; i++)
#pragma unroll
        for (int j = 0; j < 8; j++) acc[i][j] = 0.f;

    const int tx = tid & 15, ty = tid >> 4;
    const int nt = K >> 4;
    for (int t = 0; t < nt; t++) {
        As[lc+0][lr]    = pa0.x; As[lc+1][lr]    = pa0.y; As[lc+2][lr]    = pa0.z; As[lc+3][lr]    = pa0.w;
        As[lc+0][lr+64] = pa1.x; As[lc+1][lr+64] = pa1.y; As[lc+2][lr+64] = pa1.z; As[lc+3][lr+64] = pa1.w;
        Bs[lc+0][lr]    = pb0.x; Bs[lc+1][lr]    = pb0.y; Bs[lc+2][lr]    = pb0.z; Bs[lc+3][lr]    = pb0.w;
        Bs[lc+0][lr+64] = pb1.x; Bs[lc+1][lr+64] = pb1.y; Bs[lc+2][lr+64] = pb1.z; Bs[lc+3][lr+64] = pb1.w;
        __syncthreads();
        if (t + 1 < nt) {
            Ap += 16; Bp += 16;
            pa0 = *(const float4*)Ap;
            pa1 = *(const float4*)(Ap + stR);
            pb0 = *(const float4*)Bp;
            pb1 = *(const float4*)(Bp + stR);
        }
#pragma unroll
        for (int kk = 0; kk < 16; kk++) {
            float4 a0 = *(const float4*)&As[kk][ty * 8];
            float4 a1 = *(const float4*)&As[kk][ty * 8 + 4];
            float4 b0 = *(const float4*)&Bs[kk][tx * 8];
            float4 b1 = *(const float4*)&Bs[kk][tx * 8 + 4];
            float av[8] = {a0.x, a0.y, a0.z, a0.w, a1.x, a1.y, a1.z, a1.w};
            float bv[8] = {b0.x, b0.y, b0.z, b0.w, b1.x, b1.y, b1.z, b1.w};
#pragma unroll
            for (int i = 0; i < 8; i++)
#pragma unroll
                for (int j = 0; j < 8; j++)
                    acc[i][j] += av[i] * bv[j];
        }
        __syncthreads();
    }
#pragma unroll
    for (int i = 0; i < 8; i++) {
        int m = bm + ty * 8 + i;
        float*       Cr = C + (size_t)m * N + bn + tx * 8;
        const float* Rr = RES ? (Res + (size_t)m * N + bn + tx * 8) : (const float*)0;
#pragma unroll
        for (int j = 0; j < 8; j++) {
            float v = acc[i][j];
            if (BIAS) v += bias[bn + tx * 8 + j];
            if (RELU) v = fmaxf(v, 0.f);
            if (RES)  v += Rr[j];
            Cr[j] = v;
        }
    }
}

// ---------------------------------------------------------------------------
// QE[r, j] = sum_k Q[r,k] * pos_emb[k, j],  r = (t*B+b)*16 + h, j in [0,513)
// grid: (2048 row tiles of 64, 9 j tiles of 64), 256 threads, 4x4/thread
// NOTE: pos_emb rows have stride 513 (odd) -> SCALAR loads only (alignment!)
// ---------------------------------------------------------------------------
__global__ __launch_bounds__(256) void qe_kernel(
    const float* __restrict__ QKVm, const float* __restrict__ pe,
    float* __restrict__ QE)
{
    __shared__ float Qs[64][64];
    __shared__ float Ps[64][68];
    const int rt = blockIdx.x;
    const int j0 = blockIdx.y * 64;
    const int tid = threadIdx.x;
    const int i  = tid >> 2;
    const int kb = (tid & 3) << 4;

    {   // Q tile: row r = rt*64 + i  (16B-aligned: 192 & 3072 are mult of 4)
        int r = rt * 64 + i;
        int mrow = r >> 4, h = r & 15;
        const float* qp = QKVm + (size_t)mrow * QKV_N + h * 192 + kb;
#pragma unroll
        for (int q = 0; q < 4; q++)
            *(float4*)&Qs[i][kb + q * 4] = *(const float4*)(qp + q * 4);
    }
    {   // pos_emb tile: Ps[k][jj] = pe[k*513 + j0+jj]  -- scalar loads
        int k = i;
        const float* pp = pe + (size_t)k * NJ;
#pragma unroll
        for (int q = 0; q < 16; q++) {
            int jj = kb + q;
            int j = j0 + jj;
            Ps[k][jj] = (j <= 512) ? pp[j] : 0.f;
        }
    }
    __syncthreads();

    const int tx = tid & 15, ty = tid >> 4;
    float acc[4][4];
#pragma unroll
    for (int r = 0; r < 4; r++)
#pragma unroll
        for (int c = 0; c < 4; c++) acc[r][c] = 0.f;

#pragma unroll 4
    for (int k = 0; k < 64; k++) {
        float qv[4], pv[4];
#pragma unroll
        for (int r = 0; r < 4; r++) qv[r] = Qs[ty * 4 + r][k];
#pragma unroll
        for (int c = 0; c < 4; c++) pv[c] = Ps[k][tx * 4 + c];
#pragma unroll
        for (int r = 0; r < 4; r++)
#pragma unroll
            for (int c = 0; c < 4; c++)
                acc[r][c] += qv[r] * pv[c];
    }
#pragma unroll
    for (int r = 0; r < 4; r++) {
        size_t rowo = (size_t)(rt * 64 + ty * 4 + r) * NJ;
#pragma unroll
        for (int c = 0; c < 4; c++) {
            int j = j0 + tx * 4 + c;
            if (j <= 512) QE[rowo + j] = acc[r][c];
        }
    }
}

// ---------------------------------------------------------------------------
// Sliding-window attention, flash-style online softmax.
// Block: 64 queries (one b,h); 9 key tiles of 64. smem = 48KB exactly.
// logit(s,j) = (q.k_{t-512+j} + QE[q,j]) * 1/8 ; valid iff 0<=j<=512 && key>=0
// ---------------------------------------------------------------------------
__global__ __launch_bounds__(256) void attn_kernel(
    const float* __restrict__ QKVm, const float* __restrict__ QE,
    float* __restrict__ AV)
{
    __shared__ float Qs[64 * 64];   // Qs[si*64 + k]
    __shared__ float KT[64 * 64];   // KT[k*64 + kk]; reused as P[si*64 + kk]
    __shared__ float Vs[64 * 64];   // Vs[kk*64 + d]

    const int s0 = blockIdx.x * 64;
    const int g  = blockIdx.y;
    const int bh = blockIdx.z;
    const int b = bh >> 4, h = bh & 15;
    const int tid = threadIdx.x;
    const int tx = tid & 15, ty = tid >> 4;
    const int tbase = g * 512 + s0;
    const int base_key = tbase - 512;

    const int li = tid >> 2;
    const int kb = (tid & 3) << 4;

    {   // load Q tile
        int t = tbase + li;
        const float* qp = QKVm + (size_t)(t * 2 + b) * QKV_N + h * 192 + kb;
#pragma unroll
        for (int q = 0; q < 4; q++)
            *(float4*)&Qs[li * 64 + kb + q * 4] = *(const float4*)(qp + q * 4);
    }

    float O[4][4];
    float mrow[4], lrow[4];
#pragma unroll
    for (int r = 0; r < 4; r++) {
        mrow[r] = -1e30f; lrow[r] = 0.f;
#pragma unroll
        for (int c = 0; c < 4; c++) O[r][c] = 0.f;
    }
    size_t qe_base[4];
#pragma unroll
    for (int r = 0; r < 4; r++) {
        int t = tbase + ty * 4 + r;
        qe_base[r] = ((size_t)(t * 2 + b) * 16 + h) * NJ;
    }

    for (int kt = 0; kt < 9; kt++) {
        __syncthreads();    // prior PV / P reads done
        {   // load K (k-major) and V tiles, zero-fill key_time < 0
            int kk = li;
            int u = base_key + kt * 64 + kk;
            if (u >= 0) {
                const float* kp = QKVm + (size_t)(u * 2 + b) * QKV_N + h * 192 + 64 + kb;
#pragma unroll
                for (int q = 0; q < 4; q++) {
                    float4 k4 = *(const float4*)(kp + q * 4);
                    int kc = kb + q * 4;
                    KT[(kc + 0) * 64 + kk] = k4.x;
                    KT[(kc + 1) * 64 + kk] = k4.y;
                    KT[(kc + 2) * 64 + kk] = k4.z;
                    KT[(kc + 3) * 64 + kk] = k4.w;
                    *(float4*)&Vs[kk * 64 + kc] = *(const float4*)(kp + 64 + q * 4);
                }
            } else {
                float4 z = make_float4(0.f, 0.f, 0.f, 0.f);
#pragma unroll
                for (int q = 0; q < 4; q++) {
                    int kc = kb + q * 4;
                    KT[(kc + 0) * 64 + kk] = 0.f;
                    KT[(kc + 1) * 64 + kk] = 0.f;
                    KT[(kc + 2) * 64 + kk] = 0.f;
                    KT[(kc + 3) * 64 + kk] = 0.f;
                    *(float4*)&Vs[kk * 64 + kc] = z;
                }
            }
        }
        __syncthreads();

        // S = Q . K^T
        float acc[4][4];
#pragma unroll
        for (int r = 0; r < 4; r++)
#pragma unroll
            for (int c = 0; c < 4; c++) acc[r][c] = 0.f;
#pragma unroll 4
        for (int k = 0; k < 64; k++) {
            float qv[4], kv[4];
#pragma unroll
            for (int r = 0; r < 4; r++) qv[r] = Qs[(ty * 4 + r) * 64 + k];
#pragma unroll
            for (int c = 0; c < 4; c++) kv[c] = KT[k * 64 + tx * 4 + c];
#pragma unroll
            for (int r = 0; r < 4; r++)
#pragma unroll
                for (int c = 0; c < 4; c++)
                    acc[r][c] += qv[r] * kv[c];
        }

        // bias + mask + online softmax stats
#pragma unroll
        for (int r = 0; r < 4; r++) {
            int si = ty * 4 + r;
#pragma unroll
            for (int c = 0; c < 4; c++) {
                int kk = tx * 4 + c;
                int j = kt * 64 + kk - si;
                int u = base_key + kt * 64 + kk;
                if (j >= 0 && j <= 512 && u >= 0)
                    acc[r][c] = (acc[r][c] + QE[qe_base[r] + j]) * 0.125f;
                else
                    acc[r][c] = -1e30f;
            }
        }
        float mnew[4], corr[4];
#pragma unroll
        for (int r = 0; r < 4; r++) {
            float tm = fmaxf(fmaxf(acc[r][0], acc[r][1]), fmaxf(acc[r][2], acc[r][3]));
#pragma unroll
            for (int o = 1; o < 16; o <<= 1)
                tm = fmaxf(tm, __shfl_xor_sync(0xffffffffu, tm, o));
            mnew[r] = fmaxf(mrow[r], tm);
            corr[r] = __expf(mrow[r] - mnew[r]);
            float rs = 0.f;
#pragma unroll
            for (int c = 0; c < 4; c++) {
                float p = (acc[r][c] > -5e29f) ? __expf(acc[r][c] - mnew[r]) : 0.f;
                acc[r][c] = p;
                rs += p;
            }
#pragma unroll
            for (int o = 1; o < 16; o <<= 1)
                rs += __shfl_xor_sync(0xffffffffu, rs, o);
            lrow[r] = lrow[r] * corr[r] + rs;
            mrow[r] = mnew[r];
#pragma unroll
            for (int c = 0; c < 4; c++) O[r][c] *= corr[r];
        }

        __syncthreads();    // everyone done reading KT as K
#pragma unroll
        for (int r = 0; r < 4; r++)
#pragma unroll
            for (int c = 0; c < 4; c++)
                KT[(ty * 4 + r) * 64 + tx * 4 + c] = acc[r][c];
        __syncthreads();    // P visible

        // O += P . V
#pragma unroll 4
        for (int kk = 0; kk < 64; kk++) {
            float pv[4], vv[4];
#pragma unroll
            for (int r = 0; r < 4; r++) pv[r] = KT[(ty * 4 + r) * 64 + kk];
#pragma unroll
            for (int c = 0; c < 4; c++) vv[c] = Vs[kk * 64 + tx * 4 + c];
#pragma unroll
            for (int r = 0; r < 4; r++)
#pragma unroll
                for (int c = 0; c < 4; c++)
                    O[r][c] += pv[r] * vv[c];
        }
    }

#pragma unroll
    for (int r = 0; r < 4; r++) {
        int t = tbase + ty * 4 + r;
        float inv = 1.f / lrow[r];
        float* op = AV + (size_t)(t * 2 + b) * 1024 + h * 64 + tx * 4;
#pragma unroll
        for (int c = 0; c < 4; c++)
            op[c] = O[r][c] * inv;
    }
}

// ---------------------------------------------------------------------------
// nxt output: nxt[s, b*16+h, c] = QKV[(3584+s)*2+b, h*192 + 64 + c], c<128
// ---------------------------------------------------------------------------
__global__ __launch_bounds__(256) void nxt_kernel(
    const float* __restrict__ QKVm, float* __restrict__ NXT)
{
    int idx = blockIdx.x * 256 + threadIdx.x;   // 512*32*128 = 2097152
    int c  = idx & 127;
    int bh = (idx >> 7) & 31;
    int s  = idx >> 12;
    int b = bh >> 4, h = bh & 15;
    int t = 3584 + s;
    NXT[idx] = QKVm[(size_t)(t * 2 + b) * QKV_N + h * 192 + 64 + c];
}

// ---------------------------------------------------------------------------
extern "C" void kernel_launch(void* const* d_in, const int* in_sizes, int n_in,
                              void* d_out, int out_size)
{
    const float* x      = (const float*)d_in[0];
    const float* ln1_g  = (const float*)d_in[1];
    const float* ln1_b  = (const float*)d_in[2];
    const float* qkv_w  = (const float*)d_in[3];
    const float* qkv_b  = (const float*)d_in[4];
    const float* pos_emb= (const float*)d_in[5];
    const float* out_w  = (const float*)d_in[6];
    const float* ln2_g  = (const float*)d_in[7];
    const float* ln2_b  = (const float*)d_in[8];
    const float* fc1_w  = (const float*)d_in[9];
    const float* fc1_b  = (const float*)d_in[10];
    const float* fc2_w  = (const float*)d_in[11];
    const float* fc2_b  = (const float*)d_in[12];
    float* out = (float*)d_out;

    float* scratch = 0;
    cudaGetSymbolAddress((void**)&scratch, g_scratch);
    float* H    = scratch + OFF_H;
    float* AV   = scratch + OFF_ATTNV;
    float* OUT1 = scratch + OFF_OUT1;
    float* H2   = scratch + OFF_H2;
    float* QKVm = scratch + OFF_QKV;
    float* FF1  = scratch + OFF_FF1;
    float* QE   = scratch + OFF_QE;

    // 1. LN1
    ln_kernel<<<NROWS, 256>>>(x, ln1_g, ln1_b, H);
    // 2. QKV = H @ qkv_w^T + qkv_b
    sgemm_nt<true, false, false><<<dim3(QKV_N / 128, NROWS / 128), 256>>>(
        H, qkv_w, qkv_b, 0, QKVm, NROWS, QKV_N, EMB);
    // 3. QE = Q @ pos_emb
    qe_kernel<<<dim3(2048, 9), 256>>>(QKVm, pos_emb, QE);
    // 4. attention -> AV
    attn_kernel<<<dim3(8, 8, 32), 256>>>(QKVm, QE, AV);
    // 5. OUT1 = AV @ out_w^T + x
    sgemm_nt<false, false, true><<<dim3(EMB / 128, NROWS / 128), 256>>>(
        AV, out_w, 0, x, OUT1, NROWS, EMB, EMB);
    // 6. LN2
    ln_kernel<<<NROWS, 256>>>(OUT1, ln2_g, ln2_b, H2);
    // 7. FF1 = relu(H2 @ fc1_w^T + fc1_b)
    sgemm_nt<true, true, false><<<dim3(FFN_I / 128, NROWS / 128), 256>>>(
        H2, fc1_w, fc1_b, 0, FF1, NROWS, FFN_I, EMB);
    // 8. out = FF1 @ fc2_w^T + fc2_b + OUT1   (writes first 8388608 of d_out)
    sgemm_nt<true, false, true><<<dim3(EMB / 128, NROWS / 128), 256>>>(
        FF1, fc2_w, fc2_b, OUT1, out, NROWS, EMB, FFN_I);
    // 9. nxt slice -> d_out + 8388608
    nxt_kernel<<<2097152 / 256, 256>>>(QKVm, out + 8388608);
}

// round 5
// speedup vs baseline: 1.7619x; 1.7619x over previous
#include <cuda_runtime.h>
#include <cuda_bf16.h>
#include <math.h>
#include <stdint.h>

// ---------------------------------------------------------------------------
// Shapes: x (T=4096, B=2, E=1024); H=16 heads, dk=dv=64; window 512 (513 rel pos)
// QKV rows = t*B + b (8192), cols = h*192 + c  (c<64 q, 64..127 k, 128..191 v)
// ---------------------------------------------------------------------------
#define NROWS 8192
#define EMB   1024
#define QKV_N 3072
#define FFN_I 4096
#define NJ    513

// fp32 scratch offsets (floats)
#define OFF_H      0ull
#define OFF_ATTNV  8388608ull
#define OFF_OUT1   16777216ull
#define OFF_H2     25165824ull
#define OFF_QKV    33554432ull
#define OFF_FF1    58720256ull
#define OFF_QE     92274688ull
#define SCRATCH_FLOATS 159514624ull

__device__ float g_scratch[SCRATCH_FLOATS];

// split-bf16 buffers
__device__ __nv_bfloat16 g_act_hi[33554432];
__device__ __nv_bfloat16 g_act_lo[33554432];
__device__ __nv_bfloat16 g_w_hi[4194304];
__device__ __nv_bfloat16 g_w_lo[4194304];

__device__ __forceinline__ uint32_t smem_u32(const void* p) {
    uint32_t a;
    asm("{ .reg .u64 t; cvta.to.shared.u64 t, %1; cvt.u32.u64 %0, t; }" : "=r"(a) : "l"(p));
    return a;
}

// ---------------------------------------------------------------------------
// split fp32 -> (hi, lo) bf16
// ---------------------------------------------------------------------------
__global__ __launch_bounds__(256) void split_kernel(
    const float* __restrict__ X, __nv_bfloat16* __restrict__ Hi,
    __nv_bfloat16* __restrict__ Lo)
{
    int i4 = blockIdx.x * 256 + threadIdx.x;
    float4 v = ((const float4*)X)[i4];
    __nv_bfloat16 h0 = __float2bfloat16(v.x);
    __nv_bfloat16 h1 = __float2bfloat16(v.y);
    __nv_bfloat16 h2 = __float2bfloat16(v.z);
    __nv_bfloat16 h3 = __float2bfloat16(v.w);
    __nv_bfloat162 hi0; hi0.x = h0; hi0.y = h1;
    __nv_bfloat162 hi1; hi1.x = h2; hi1.y = h3;
    __nv_bfloat162 lo0, lo1;
    lo0.x = __float2bfloat16(v.x - __bfloat162float(h0));
    lo0.y = __float2bfloat16(v.y - __bfloat162float(h1));
    lo1.x = __float2bfloat16(v.z - __bfloat162float(h2));
    lo1.y = __float2bfloat16(v.w - __bfloat162float(h3));
    ((__nv_bfloat162*)Hi)[i4 * 2]     = hi0;
    ((__nv_bfloat162*)Hi)[i4 * 2 + 1] = hi1;
    ((__nv_bfloat162*)Lo)[i4 * 2]     = lo0;
    ((__nv_bfloat162*)Lo)[i4 * 2 + 1] = lo1;
}

// ---------------------------------------------------------------------------
// mma.sync bf16 split GEMM NT: C[M,N] = (Ah+Al)(Bh+Bl)^T (+bias)(relu)(+Res)
// CTA 128x128, BK=32, 8 warps (64x32 each), cp.async double buffer.
// smem tile layout: row-major [128][32] bf16, 64B/row,
//   16B chunk c at phys chunk (c ^ ((row>>1)&3))  -> ldmatrix conflict-free.
// ---------------------------------------------------------------------------
#define STAGE_BYTES 32768
#define MMA_SMEM    65536

__device__ __forceinline__ void cp16(uint32_t dst, const void* src) {
    asm volatile("cp.async.cg.shared.global [%0], [%1], 16;" :: "r"(dst), "l"(src));
}
__device__ __forceinline__ void ldm4(uint32_t* r, uint32_t addr) {
    asm volatile("ldmatrix.sync.aligned.m8n8.x4.shared.b16 {%0,%1,%2,%3}, [%4];"
                 : "=r"(r[0]), "=r"(r[1]), "=r"(r[2]), "=r"(r[3]) : "r"(addr));
}
__device__ __forceinline__ void mma16816(float* c, const uint32_t* a,
                                         uint32_t b0, uint32_t b1) {
    asm volatile(
        "mma.sync.aligned.m16n8k16.row.col.f32.bf16.bf16.f32 "
        "{%0,%1,%2,%3}, {%4,%5,%6,%7}, {%8,%9}, {%0,%1,%2,%3};"
        : "+f"(c[0]), "+f"(c[1]), "+f"(c[2]), "+f"(c[3])
        : "r"(a[0]), "r"(a[1]), "r"(a[2]), "r"(a[3]), "r"(b0), "r"(b1));
}

template<bool BIAS, bool RELU, bool RES>
__global__ __launch_bounds__(256, 1) void mma_gemm(
    const __nv_bfloat16* __restrict__ Ah, const __nv_bfloat16* __restrict__ Al,
    const __nv_bfloat16* __restrict__ Bh, const __nv_bfloat16* __restrict__ Bl,
    const float* __restrict__ bias, const float* __restrict__ Res,
    float* __restrict__ C, int M, int N, int K)
{
    extern __shared__ char smem[];
    const uint32_t sbase = smem_u32(smem);
    const int tid = threadIdx.x;
    const int wid = tid >> 5, lane = tid & 31;
    const int bm = blockIdx.y * 128, bn = blockIdx.x * 128;
    const int m0w = (wid >> 2) * 64, n0w = (wid & 3) * 32;

    // load indexing: idx -> row (0..127), chunk (0..3); 2 idx per thread
    const int r0 = tid >> 2,        c0 = tid & 3;
    const int r1 = (tid + 256) >> 2, c1 = (tid + 256) & 3;
    const uint32_t so0 = (uint32_t)(r0 * 64 + ((c0 ^ ((r0 >> 1) & 3)) * 16));
    const uint32_t so1 = (uint32_t)(r1 * 64 + ((c1 ^ ((r1 >> 1) & 3)) * 16));

    const __nv_bfloat16* gA0h = Ah + (size_t)(bm + r0) * K + c0 * 8;
    const __nv_bfloat16* gA1h = Ah + (size_t)(bm + r1) * K + c1 * 8;
    const __nv_bfloat16* gA0l = Al + (size_t)(bm + r0) * K + c0 * 8;
    const __nv_bfloat16* gA1l = Al + (size_t)(bm + r1) * K + c1 * 8;
    const __nv_bfloat16* gB0h = Bh + (size_t)(bn + r0) * K + c0 * 8;
    const __nv_bfloat16* gB1h = Bh + (size_t)(bn + r1) * K + c1 * 8;
    const __nv_bfloat16* gB0l = Bl + (size_t)(bn + r0) * K + c0 * 8;
    const __nv_bfloat16* gB1l = Bl + (size_t)(bn + r1) * K + c1 * 8;

    float acc[4][4][4];
#pragma unroll
    for (int a = 0; a < 4; a++)
#pragma unroll
        for (int n = 0; n < 4; n++)
#pragma unroll
            for (int q = 0; q < 4; q++) acc[a][n][q] = 0.f;

    const int nt = K >> 5;

    // ldmatrix address precompute (per warp)
    const int rowA_base = m0w + (lane & 15);
    const int rowB_base = n0w + (lane & 15);
    const int chsel = lane >> 4;    // 0/1: k-halves

#define LOAD_STAGE(s, k0)                                                     \
    do {                                                                      \
        uint32_t d = sbase + (s) * STAGE_BYTES;                               \
        cp16(d + so0,          gA0h + (k0));                                  \
        cp16(d + so1,          gA1h + (k0));                                  \
        cp16(d + 8192  + so0,  gA0l + (k0));                                  \
        cp16(d + 8192  + so1,  gA1l + (k0));                                  \
        cp16(d + 16384 + so0,  gB0h + (k0));                                  \
        cp16(d + 16384 + so1,  gB1h + (k0));                                  \
        cp16(d + 24576 + so0,  gB0l + (k0));                                  \
        cp16(d + 24576 + so1,  gB1l + (k0));                                  \
    } while (0)

    LOAD_STAGE(0, 0);
    asm volatile("cp.async.commit_group;");
    if (nt > 1) LOAD_STAGE(1, 32);
    asm volatile("cp.async.commit_group;");

    for (int i = 0; i < nt; i++) {
        asm volatile("cp.async.wait_group 1;");
        __syncthreads();
        uint32_t base = sbase + (i & 1) * STAGE_BYTES;
#pragma unroll
        for (int ks = 0; ks < 2; ks++) {
            const int chunk = ks * 2 + chsel;
            uint32_t ah[4][4], al[4][4], bh[2][4], bl[2][4];
#pragma unroll
            for (int a = 0; a < 4; a++) {
                int row = rowA_base + a * 16;
                uint32_t ad = base + (uint32_t)(row * 64 + ((chunk ^ ((row >> 1) & 3)) * 16));
                ldm4(ah[a], ad);
                ldm4(al[a], ad + 8192);
            }
#pragma unroll
            for (int p = 0; p < 2; p++) {
                int row = rowB_base + p * 16;
                uint32_t ad = base + 16384 + (uint32_t)(row * 64 + ((chunk ^ ((row >> 1) & 3)) * 16));
                ldm4(bh[p], ad);
                ldm4(bl[p], ad + 8192);
            }
#pragma unroll
            for (int a = 0; a < 4; a++) {
#pragma unroll
                for (int n = 0; n < 4; n++) {
                    int p = n >> 1, q = n & 1;
                    mma16816(acc[a][n], ah[a], bh[p][q], bh[p][q + 2]);
                    mma16816(acc[a][n], ah[a], bl[p][q], bl[p][q + 2]);
                    mma16816(acc[a][n], al[a], bh[p][q], bh[p][q + 2]);
                }
            }
        }
        __syncthreads();
        if (i + 2 < nt) LOAD_STAGE(i & 1, (i + 2) << 5);
        asm volatile("cp.async.commit_group;");
    }
#undef LOAD_STAGE

    // epilogue
    const int g = lane >> 2, t = lane & 3;
#pragma unroll
    for (int a = 0; a < 4; a++) {
#pragma unroll
        for (int n = 0; n < 4; n++) {
            int row0 = bm + m0w + a * 16 + g;
            int col  = bn + n0w + n * 8 + 2 * t;
            float v0 = acc[a][n][0], v1 = acc[a][n][1];
            float v2 = acc[a][n][2], v3 = acc[a][n][3];
            if (BIAS) {
                float b0 = bias[col], b1 = bias[col + 1];
                v0 += b0; v1 += b1; v2 += b0; v3 += b1;
            }
            if (RELU) {
                v0 = fmaxf(v0, 0.f); v1 = fmaxf(v1, 0.f);
                v2 = fmaxf(v2, 0.f); v3 = fmaxf(v3, 0.f);
            }
            if (RES) {
                const float2 q0 = *(const float2*)(Res + (size_t)row0 * N + col);
                const float2 q1 = *(const float2*)(Res + (size_t)(row0 + 8) * N + col);
                v0 += q0.x; v1 += q0.y; v2 += q1.x; v3 += q1.y;
            }
            float2 o0; o0.x = v0; o0.y = v1;
            float2 o1; o1.x = v2; o1.y = v3;
            *(float2*)(C + (size_t)row0 * N + col)       = o0;
            *(float2*)(C + (size_t)(row0 + 8) * N + col) = o1;
        }
    }
}

// ---------------------------------------------------------------------------
// LayerNorm
// ---------------------------------------------------------------------------
__global__ __launch_bounds__(256) void ln_kernel(
    const float* __restrict__ X, const float* __restrict__ G,
    const float* __restrict__ Bt, float* __restrict__ Y)
{
    __shared__ float ssum[8], ssq[8], smv[2];
    int row = blockIdx.x;
    int tid = threadIdx.x;
    const float4* xr = (const float4*)(X + (size_t)row * EMB);
    float4 v = xr[tid];
    float s = v.x + v.y + v.z + v.w;
    float q = v.x*v.x + v.y*v.y + v.z*v.z + v.w*v.w;
#pragma unroll
    for (int o = 16; o > 0; o >>= 1) {
        s += __shfl_xor_sync(0xffffffffu, s, o);
        q += __shfl_xor_sync(0xffffffffu, q, o);
    }
    if ((tid & 31) == 0) { ssum[tid >> 5] = s; ssq[tid >> 5] = q; }
    __syncthreads();
    if (tid == 0) {
        float S = 0.f, Q = 0.f;
#pragma unroll
        for (int i = 0; i < 8; i++) { S += ssum[i]; Q += ssq[i]; }
        float mean = S * (1.f / EMB);
        float var  = Q * (1.f / EMB) - mean * mean;
        smv[0] = mean;
        smv[1] = rsqrtf(var + 1e-5f);
    }
    __syncthreads();
    float mean = smv[0], inv = smv[1];
    float4 g = ((const float4*)G)[tid];
    float4 b = ((const float4*)Bt)[tid];
    float4 o;
    o.x = (v.x - mean) * inv * g.x + b.x;
    o.y = (v.y - mean) * inv * g.y + b.y;
    o.z = (v.z - mean) * inv * g.z + b.z;
    o.w = (v.w - mean) * inv * g.w + b.w;
    ((float4*)(Y + (size_t)row * EMB))[tid] = o;
}

// ---------------------------------------------------------------------------
// QE[r, j] = sum_k Q[r,k] * pos_emb[k, j]  (pe rows stride 513: scalar loads)
// ---------------------------------------------------------------------------
__global__ __launch_bounds__(256) void qe_kernel(
    const float* __restrict__ QKVm, const float* __restrict__ pe,
    float* __restrict__ QE)
{
    __shared__ float Qs[64][64];
    __shared__ float Ps[64][68];
    const int rt = blockIdx.x;
    const int j0 = blockIdx.y * 64;
    const int tid = threadIdx.x;
    const int i  = tid >> 2;
    const int kb = (tid & 3) << 4;

    {
        int r = rt * 64 + i;
        int mrow = r >> 4, h = r & 15;
        const float* qp = QKVm + (size_t)mrow * QKV_N + h * 192 + kb;
#pragma unroll
        for (int q = 0; q < 4; q++)
            *(float4*)&Qs[i][kb + q * 4] = *(const float4*)(qp + q * 4);
    }
    {
        int k = i;
        const float* pp = pe + (size_t)k * NJ;
#pragma unroll
        for (int q = 0; q < 16; q++) {
            int jj = kb + q;
            int j = j0 + jj;
            Ps[k][jj] = (j <= 512) ? pp[j] : 0.f;
        }
    }
    __syncthreads();

    const int tx = tid & 15, ty = tid >> 4;
    float acc[4][4];
#pragma unroll
    for (int r = 0; r < 4; r++)
#pragma unroll
        for (int c = 0; c < 4; c++) acc[r][c] = 0.f;

#pragma unroll 4
    for (int k = 0; k < 64; k++) {
        float qv[4], pv[4];
#pragma unroll
        for (int r = 0; r < 4; r++) qv[r] = Qs[ty * 4 + r][k];
#pragma unroll
        for (int c = 0; c < 4; c++) pv[c] = Ps[k][tx * 4 + c];
#pragma unroll
        for (int r = 0; r < 4; r++)
#pragma unroll
            for (int c = 0; c < 4; c++)
                acc[r][c] += qv[r] * pv[c];
    }
#pragma unroll
    for (int r = 0; r < 4; r++) {
        size_t rowo = (size_t)(rt * 64 + ty * 4 + r) * NJ;
#pragma unroll
        for (int c = 0; c < 4; c++) {
            int j = j0 + tx * 4 + c;
            if (j <= 512) QE[rowo + j] = acc[r][c];
        }
    }
}

// ---------------------------------------------------------------------------
// Sliding-window attention (flash-style, unchanged, passing)
// ---------------------------------------------------------------------------
__global__ __launch_bounds__(256) void attn_kernel(
    const float* __restrict__ QKVm, const float* __restrict__ QE,
    float* __restrict__ AV)
{
    __shared__ float Qs[64 * 64];
    __shared__ float KT[64 * 64];
    __shared__ float Vs[64 * 64];

    const int s0 = blockIdx.x * 64;
    const int g  = blockIdx.y;
    const int bh = blockIdx.z;
    const int b = bh >> 4, h = bh & 15;
    const int tid = threadIdx.x;
    const int tx = tid & 15, ty = tid >> 4;
    const int tbase = g * 512 + s0;
    const int base_key = tbase - 512;

    const int li = tid >> 2;
    const int kb = (tid & 3) << 4;

    {
        int t = tbase + li;
        const float* qp = QKVm + (size_t)(t * 2 + b) * QKV_N + h * 192 + kb;
#pragma unroll
        for (int q = 0; q < 4; q++)
            *(float4*)&Qs[li * 64 + kb + q * 4] = *(const float4*)(qp + q * 4);
    }

    float O[4][4];
    float mrow[4], lrow[4];
#pragma unroll
    for (int r = 0; r < 4; r++) {
        mrow[r] = -1e30f; lrow[r] = 0.f;
#pragma unroll
        for (int c = 0; c < 4; c++) O[r][c] = 0.f;
    }
    size_t qe_base[4];
#pragma unroll
    for (int r = 0; r < 4; r++) {
        int t = tbase + ty * 4 + r;
        qe_base[r] = ((size_t)(t * 2 + b) * 16 + h) * NJ;
    }

    for (int kt = 0; kt < 9; kt++) {
        __syncthreads();
        {
            int kk = li;
            int u = base_key + kt * 64 + kk;
            if (u >= 0) {
                const float* kp = QKVm + (size_t)(u * 2 + b) * QKV_N + h * 192 + 64 + kb;
#pragma unroll
                for (int q = 0; q < 4; q++) {
                    float4 k4 = *(const float4*)(kp + q * 4);
                    int kc = kb + q * 4;
                    KT[(kc + 0) * 64 + kk] = k4.x;
                    KT[(kc + 1) * 64 + kk] = k4.y;
                    KT[(kc + 2) * 64 + kk] = k4.z;
                    KT[(kc + 3) * 64 + kk] = k4.w;
                    *(float4*)&Vs[kk * 64 + kc] = *(const float4*)(kp + 64 + q * 4);
                }
            } else {
                float4 z = make_float4(0.f, 0.f, 0.f, 0.f);
#pragma unroll
                for (int q = 0; q < 4; q++) {
                    int kc = kb + q * 4;
                    KT[(kc + 0) * 64 + kk] = 0.f;
                    KT[(kc + 1) * 64 + kk] = 0.f;
                    KT[(kc + 2) * 64 + kk] = 0.f;
                    KT[(kc + 3) * 64 + kk] = 0.f;
                    *(float4*)&Vs[kk * 64 + kc] = z;
                }
            }
        }
        __syncthreads();

        float acc[4][4];
#pragma unroll
        for (int r = 0; r < 4; r++)
#pragma unroll
            for (int c = 0; c < 4; c++) acc[r][c] = 0.f;
#pragma unroll 4
        for (int k = 0; k < 64; k++) {
            float qv[4], kv[4];
#pragma unroll
            for (int r = 0; r < 4; r++) qv[r] = Qs[(ty * 4 + r) * 64 + k];
#pragma unroll
            for (int c = 0; c < 4; c++) kv[c] = KT[k * 64 + tx * 4 + c];
#pragma unroll
            for (int r = 0; r < 4; r++)
#pragma unroll
                for (int c = 0; c < 4; c++)
                    acc[r][c] += qv[r] * kv[c];
        }

#pragma unroll
        for (int r = 0; r < 4; r++) {
            int si = ty * 4 + r;
#pragma unroll
            for (int c = 0; c < 4; c++) {
                int kk = tx * 4 + c;
                int j = kt * 64 + kk - si;
                int u = base_key + kt * 64 + kk;
                if (j >= 0 && j <= 512 && u >= 0)
                    acc[r][c] = (acc[r][c] + QE[qe_base[r] + j]) * 0.125f;
                else
                    acc[r][c] = -1e30f;
            }
        }
        float mnew[4], corr[4];
#pragma unroll
        for (int r = 0; r < 4; r++) {
            float tm = fmaxf(fmaxf(acc[r][0], acc[r][1]), fmaxf(acc[r][2], acc[r][3]));
#pragma unroll
            for (int o = 1; o < 16; o <<= 1)
                tm = fmaxf(tm, __shfl_xor_sync(0xffffffffu, tm, o));
            mnew[r] = fmaxf(mrow[r], tm);
            corr[r] = __expf(mrow[r] - mnew[r]);
            float rs = 0.f;
#pragma unroll
            for (int c = 0; c < 4; c++) {
                float p = (acc[r][c] > -5e29f) ? __expf(acc[r][c] - mnew[r]) : 0.f;
                acc[r][c] = p;
                rs += p;
            }
#pragma unroll
            for (int o = 1; o < 16; o <<= 1)
                rs += __shfl_xor_sync(0xffffffffu, rs, o);
            lrow[r] = lrow[r] * corr[r] + rs;
            mrow[r] = mnew[r];
#pragma unroll
            for (int c = 0; c < 4; c++) O[r][c] *= corr[r];
        }

        __syncthreads();
#pragma unroll
        for (int r = 0; r < 4; r++)
#pragma unroll
            for (int c = 0; c < 4; c++)
                KT[(ty * 4 + r) * 64 + tx * 4 + c] = acc[r][c];
        __syncthreads();

#pragma unroll 4
        for (int kk = 0; kk < 64; kk++) {
            float pv[4], vv[4];
#pragma unroll
            for (int r = 0; r < 4; r++) pv[r] = KT[(ty * 4 + r) * 64 + kk];
#pragma unroll
            for (int c = 0; c < 4; c++) vv[c] = Vs[kk * 64 + tx * 4 + c];
#pragma unroll
            for (int r = 0; r < 4; r++)
#pragma unroll
                for (int c = 0; c < 4; c++)
                    O[r][c] += pv[r] * vv[c];
        }
    }

#pragma unroll
    for (int r = 0; r < 4; r++) {
        int t = tbase + ty * 4 + r;
        float inv = 1.f / lrow[r];
        float* op = AV + (size_t)(t * 2 + b) * 1024 + h * 64 + tx * 4;
#pragma unroll
        for (int c = 0; c < 4; c++)
            op[c] = O[r][c] * inv;
    }
}

// ---------------------------------------------------------------------------
// nxt output copy
// ---------------------------------------------------------------------------
__global__ __launch_bounds__(256) void nxt_kernel(
    const float* __restrict__ QKVm, float* __restrict__ NXT)
{
    int idx = blockIdx.x * 256 + threadIdx.x;
    int c  = idx & 127;
    int bh = (idx >> 7) & 31;
    int s  = idx >> 12;
    int b = bh >> 4, h = bh & 15;
    int t = 3584 + s;
    NXT[idx] = QKVm[(size_t)(t * 2 + b) * QKV_N + h * 192 + 64 + c];
}

// ---------------------------------------------------------------------------
extern "C" void kernel_launch(void* const* d_in, const int* in_sizes, int n_in,
                              void* d_out, int out_size)
{
    const float* x      = (const float*)d_in[0];
    const float* ln1_g  = (const float*)d_in[1];
    const float* ln1_b  = (const float*)d_in[2];
    const float* qkv_w  = (const float*)d_in[3];
    const float* qkv_b  = (const float*)d_in[4];
    const float* pos_emb= (const float*)d_in[5];
    const float* out_w  = (const float*)d_in[6];
    const float* ln2_g  = (const float*)d_in[7];
    const float* ln2_b  = (const float*)d_in[8];
    const float* fc1_w  = (const float*)d_in[9];
    const float* fc1_b  = (const float*)d_in[10];
    const float* fc2_w  = (const float*)d_in[11];
    const float* fc2_b  = (const float*)d_in[12];
    float* out = (float*)d_out;

    float* scratch = 0;
    cudaGetSymbolAddress((void**)&scratch, g_scratch);
    __nv_bfloat16 *Ahi, *Alo, *Whi, *Wlo;
    cudaGetSymbolAddress((void**)&Ahi, g_act_hi);
    cudaGetSymbolAddress((void**)&Alo, g_act_lo);
    cudaGetSymbolAddress((void**)&Whi, g_w_hi);
    cudaGetSymbolAddress((void**)&Wlo, g_w_lo);

    float* H    = scratch + OFF_H;
    float* AV   = scratch + OFF_ATTNV;
    float* OUT1 = scratch + OFF_OUT1;
    float* H2   = scratch + OFF_H2;
    float* QKVm = scratch + OFF_QKV;
    float* FF1  = scratch + OFF_FF1;
    float* QE   = scratch + OFF_QE;

    cudaFuncSetAttribute(mma_gemm<true, false, false>, cudaFuncAttributeMaxDynamicSharedMemorySize, MMA_SMEM);
    cudaFuncSetAttribute(mma_gemm<false, false, true>, cudaFuncAttributeMaxDynamicSharedMemorySize, MMA_SMEM);
    cudaFuncSetAttribute(mma_gemm<true, true, false>,  cudaFuncAttributeMaxDynamicSharedMemorySize, MMA_SMEM);
    cudaFuncSetAttribute(mma_gemm<true, false, true>,  cudaFuncAttributeMaxDynamicSharedMemorySize, MMA_SMEM);

    // 1. LN1
    ln_kernel<<<NROWS, 256>>>(x, ln1_g, ln1_b, H);
    // 2. QKV = H @ qkv_w^T + qkv_b
    split_kernel<<<(NROWS * EMB) / 1024, 256>>>(H, Ahi, Alo);
    split_kernel<<<(QKV_N * EMB) / 1024, 256>>>(qkv_w, Whi, Wlo);
    mma_gemm<true, false, false><<<dim3(QKV_N / 128, NROWS / 128), 256, MMA_SMEM>>>(
        Ahi, Alo, Whi, Wlo, qkv_b, 0, QKVm, NROWS, QKV_N, EMB);
    // 3. QE = Q @ pos_emb
    qe_kernel<<<dim3(2048, 9), 256>>>(QKVm, pos_emb, QE);
    // 4. attention -> AV
    attn_kernel<<<dim3(8, 8, 32), 256>>>(QKVm, QE, AV);
    // 5. OUT1 = AV @ out_w^T + x
    split_kernel<<<(NROWS * EMB) / 1024, 256>>>(AV, Ahi, Alo);
    split_kernel<<<(EMB * EMB) / 1024, 256>>>(out_w, Whi, Wlo);
    mma_gemm<false, false, true><<<dim3(EMB / 128, NROWS / 128), 256, MMA_SMEM>>>(
        Ahi, Alo, Whi, Wlo, 0, x, OUT1, NROWS, EMB, EMB);
    // 6. LN2
    ln_kernel<<<NROWS, 256>>>(OUT1, ln2_g, ln2_b, H2);
    // 7. FF1 = relu(H2 @ fc1_w^T + fc1_b)
    split_kernel<<<(NROWS * EMB) / 1024, 256>>>(H2, Ahi, Alo);
    split_kernel<<<(FFN_I * EMB) / 1024, 256>>>(fc1_w, Whi, Wlo);
    mma_gemm<true, true, false><<<dim3(FFN_I / 128, NROWS / 128), 256, MMA_SMEM>>>(
        Ahi, Alo, Whi, Wlo, fc1_b, 0, FF1, NROWS, FFN_I, EMB);
    // 8. out = FF1 @ fc2_w^T + fc2_b + OUT1
    split_kernel<<<(NROWS * FFN_I) / 1024, 256>>>(FF1, Ahi, Alo);
    split_kernel<<<(EMB * FFN_I) / 1024, 256>>>(fc2_w, Whi, Wlo);
    mma_gemm<true, false, true><<<dim3(EMB / 128, NROWS / 128), 256, MMA_SMEM>>>(
        Ahi, Alo, Whi, Wlo, fc2_b, OUT1, out, NROWS, EMB, FFN_I);
    // 9. nxt slice
    nxt_kernel<<<2097152 / 256, 256>>>(QKVm, out + 8388608);
}

// round 6
// speedup vs baseline: 1.9181x; 1.0886x over previous
#include <cuda_runtime.h>
#include <cuda_bf16.h>
#include <math.h>
#include <stdint.h>

// ---------------------------------------------------------------------------
// Shapes: x (T=4096, B=2, E=1024); H=16 heads, dk=dv=64; window 512 (513 rel pos)
// QKV rows = t*B + b (8192), cols = h*192 + c  (c<64 q, 64..127 k, 128..191 v)
// ---------------------------------------------------------------------------
#define NROWS 8192
#define EMB   1024
#define QKV_N 3072
#define FFN_I 4096
#define NJ    513

// fp32 scratch offsets (floats)
#define OFF_OUT1   16777216ull
#define OFF_QKV    33554432ull
#define OFF_QE     92274688ull
#define SCRATCH_FLOATS 159514624ull

__device__ float g_scratch[SCRATCH_FLOATS];

// split-bf16 buffers
__device__ __nv_bfloat16 g_act_hi[8388608];    // activations (<=8192x1024)
__device__ __nv_bfloat16 g_act_lo[8388608];
__device__ __nv_bfloat16 g_act2_hi[33554432];  // fc1 output (8192x4096)
__device__ __nv_bfloat16 g_act2_lo[33554432];
__device__ __nv_bfloat16 g_w_hi[4194304];
__device__ __nv_bfloat16 g_w_lo[4194304];

__device__ __forceinline__ uint32_t smem_u32(const void* p) {
    uint32_t a;
    asm("{ .reg .u64 t; cvta.to.shared.u64 t, %1; cvt.u32.u64 %0, t; }" : "=r"(a) : "l"(p));
    return a;
}

__device__ __forceinline__ void split1(float v, __nv_bfloat16& h, __nv_bfloat16& l) {
    h = __float2bfloat16(v);
    l = __float2bfloat16(v - __bfloat162float(h));
}

// ---------------------------------------------------------------------------
// split fp32 -> (hi, lo) bf16   (used for weights)
// ---------------------------------------------------------------------------
__global__ __launch_bounds__(256) void split_kernel(
    const float* __restrict__ X, __nv_bfloat16* __restrict__ Hi,
    __nv_bfloat16* __restrict__ Lo)
{
    int i4 = blockIdx.x * 256 + threadIdx.x;
    float4 v = ((const float4*)X)[i4];
    __nv_bfloat162 hi0, hi1, lo0, lo1;
    split1(v.x, hi0.x, lo0.x);
    split1(v.y, hi0.y, lo0.y);
    split1(v.z, hi1.x, lo1.x);
    split1(v.w, hi1.y, lo1.y);
    ((__nv_bfloat162*)Hi)[i4 * 2]     = hi0;
    ((__nv_bfloat162*)Hi)[i4 * 2 + 1] = hi1;
    ((__nv_bfloat162*)Lo)[i4 * 2]     = lo0;
    ((__nv_bfloat162*)Lo)[i4 * 2 + 1] = lo1;
}

// ---------------------------------------------------------------------------
// LayerNorm fused with split: X fp32 row -> (hi, lo) bf16 row
// ---------------------------------------------------------------------------
__global__ __launch_bounds__(256) void ln_split_kernel(
    const float* __restrict__ X, const float* __restrict__ G,
    const float* __restrict__ Bt, __nv_bfloat16* __restrict__ Hi,
    __nv_bfloat16* __restrict__ Lo)
{
    __shared__ float ssum[8], ssq[8], smv[2];
    int row = blockIdx.x;
    int tid = threadIdx.x;
    const float4* xr = (const float4*)(X + (size_t)row * EMB);
    float4 v = xr[tid];
    float s = v.x + v.y + v.z + v.w;
    float q = v.x*v.x + v.y*v.y + v.z*v.z + v.w*v.w;
#pragma unroll
    for (int o = 16; o > 0; o >>= 1) {
        s += __shfl_xor_sync(0xffffffffu, s, o);
        q += __shfl_xor_sync(0xffffffffu, q, o);
    }
    if ((tid & 31) == 0) { ssum[tid >> 5] = s; ssq[tid >> 5] = q; }
    __syncthreads();
    if (tid == 0) {
        float S = 0.f, Q = 0.f;
#pragma unroll
        for (int i = 0; i < 8; i++) { S += ssum[i]; Q += ssq[i]; }
        float mean = S * (1.f / EMB);
        float var  = Q * (1.f / EMB) - mean * mean;
        smv[0] = mean;
        smv[1] = rsqrtf(var + 1e-5f);
    }
    __syncthreads();
    float mean = smv[0], inv = smv[1];
    float4 g = ((const float4*)G)[tid];
    float4 b = ((const float4*)Bt)[tid];
    float o0 = (v.x - mean) * inv * g.x + b.x;
    float o1 = (v.y - mean) * inv * g.y + b.y;
    float o2 = (v.z - mean) * inv * g.z + b.z;
    float o3 = (v.w - mean) * inv * g.w + b.w;
    __nv_bfloat162 hi0, hi1, lo0, lo1;
    split1(o0, hi0.x, lo0.x);
    split1(o1, hi0.y, lo0.y);
    split1(o2, hi1.x, lo1.x);
    split1(o3, hi1.y, lo1.y);
    size_t i4 = (size_t)row * 256 + tid;
    ((__nv_bfloat162*)Hi)[i4 * 2]     = hi0;
    ((__nv_bfloat162*)Hi)[i4 * 2 + 1] = hi1;
    ((__nv_bfloat162*)Lo)[i4 * 2]     = lo0;
    ((__nv_bfloat162*)Lo)[i4 * 2 + 1] = lo1;
}

// ---------------------------------------------------------------------------
// mma.sync bf16 split GEMM NT: C = (Ah+Al)(Bh+Bl)^T (+bias)(relu)(+Res)
// CTA 128x128, BK=32, 8 warps (64x32 each), cp.async double buffer.
// SPLITO: write (hi,lo) bf16 instead of fp32 C.
// ---------------------------------------------------------------------------
#define STAGE_BYTES 32768
#define MMA_SMEM    65536

__device__ __forceinline__ void cp16(uint32_t dst, const void* src) {
    asm volatile("cp.async.cg.shared.global [%0], [%1], 16;" :: "r"(dst), "l"(src));
}
__device__ __forceinline__ void ldm4(uint32_t* r, uint32_t addr) {
    asm volatile("ldmatrix.sync.aligned.m8n8.x4.shared.b16 {%0,%1,%2,%3}, [%4];"
                 : "=r"(r[0]), "=r"(r[1]), "=r"(r[2]), "=r"(r[3]) : "r"(addr));
}
__device__ __forceinline__ void mma16816(float* c, const uint32_t* a,
                                         uint32_t b0, uint32_t b1) {
    asm volatile(
        "mma.sync.aligned.m16n8k16.row.col.f32.bf16.bf16.f32 "
        "{%0,%1,%2,%3}, {%4,%5,%6,%7}, {%8,%9}, {%0,%1,%2,%3};"
        : "+f"(c[0]), "+f"(c[1]), "+f"(c[2]), "+f"(c[3])
        : "r"(a[0]), "r"(a[1]), "r"(a[2]), "r"(a[3]), "r"(b0), "r"(b1));
}

template<bool BIAS, bool RELU, bool RES, bool SPLITO>
__global__ __launch_bounds__(256, 2) void mma_gemm(
    const __nv_bfloat16* __restrict__ Ah, const __nv_bfloat16* __restrict__ Al,
    const __nv_bfloat16* __restrict__ Bh, const __nv_bfloat16* __restrict__ Bl,
    const float* __restrict__ bias, const float* __restrict__ Res,
    float* __restrict__ C, __nv_bfloat16* __restrict__ OHi,
    __nv_bfloat16* __restrict__ OLo, int M, int N, int K)
{
    extern __shared__ char smem[];
    const uint32_t sbase = smem_u32(smem);
    const int tid = threadIdx.x;
    const int wid = tid >> 5, lane = tid & 31;
    const int bm = blockIdx.y * 128, bn = blockIdx.x * 128;
    const int m0w = (wid >> 2) * 64, n0w = (wid & 3) * 32;

    // load indexing: idx -> row (0..127), chunk (0..3); 2 idx per thread
    const int r0 = tid >> 2,         c0 = tid & 3;
    const int r1 = (tid + 256) >> 2, c1 = (tid + 256) & 3;
    const uint32_t so0 = (uint32_t)(r0 * 64 + ((c0 ^ ((r0 >> 1) & 3)) * 16));
    const uint32_t so1 = (uint32_t)(r1 * 64 + ((c1 ^ ((r1 >> 1) & 3)) * 16));
    const size_t offA0 = (size_t)(bm + r0) * K + c0 * 8;
    const size_t offA1 = (size_t)(bm + r1) * K + c1 * 8;
    const size_t offB0 = (size_t)(bn + r0) * K + c0 * 8;
    const size_t offB1 = (size_t)(bn + r1) * K + c1 * 8;

    float acc[4][4][4];
#pragma unroll
    for (int a = 0; a < 4; a++)
#pragma unroll
        for (int n = 0; n < 4; n++)
#pragma unroll
            for (int q = 0; q < 4; q++) acc[a][n][q] = 0.f;

    const int nt = K >> 5;
    const int rowA_base = m0w + (lane & 15);
    const int rowB_base = n0w + (lane & 15);
    const int chsel = lane >> 4;

#define LOAD_STAGE(s, k0)                                                     \
    do {                                                                      \
        uint32_t d = sbase + (s) * STAGE_BYTES;                               \
        cp16(d + so0,          Ah + offA0 + (k0));                            \
        cp16(d + so1,          Ah + offA1 + (k0));                            \
        cp16(d + 8192  + so0,  Al + offA0 + (k0));                            \
        cp16(d + 8192  + so1,  Al + offA1 + (k0));                            \
        cp16(d + 16384 + so0,  Bh + offB0 + (k0));                            \
        cp16(d + 16384 + so1,  Bh + offB1 + (k0));                            \
        cp16(d + 24576 + so0,  Bl + offB0 + (k0));                            \
        cp16(d + 24576 + so1,  Bl + offB1 + (k0));                            \
    } while (0)

    LOAD_STAGE(0, 0);
    asm volatile("cp.async.commit_group;");
    if (nt > 1) LOAD_STAGE(1, 32);
    asm volatile("cp.async.commit_group;");

    for (int i = 0; i < nt; i++) {
        asm volatile("cp.async.wait_group 1;");
        __syncthreads();
        uint32_t base = sbase + (i & 1) * STAGE_BYTES;
#pragma unroll
        for (int ks = 0; ks < 2; ks++) {
            const int chunk = ks * 2 + chsel;
            uint32_t bh[2][4], bl[2][4];
#pragma unroll
            for (int p = 0; p < 2; p++) {
                int row = rowB_base + p * 16;
                uint32_t ad = base + 16384 + (uint32_t)(row * 64 + ((chunk ^ ((row >> 1) & 3)) * 16));
                ldm4(bh[p], ad);
                ldm4(bl[p], ad + 8192);
            }
            // per-a strip: A fragments live only inside this iteration
#pragma unroll
            for (int a = 0; a < 4; a++) {
                uint32_t ah[4], al[4];
                int row = rowA_base + a * 16;
                uint32_t ad = base + (uint32_t)(row * 64 + ((chunk ^ ((row >> 1) & 3)) * 16));
                ldm4(ah, ad);
                ldm4(al, ad + 8192);
#pragma unroll
                for (int n = 0; n < 4; n++) {
                    int p = n >> 1, q = n & 1;
                    mma16816(acc[a][n], ah, bh[p][q], bh[p][q + 2]);
                    mma16816(acc[a][n], ah, bl[p][q], bl[p][q + 2]);
                    mma16816(acc[a][n], al, bh[p][q], bh[p][q + 2]);
                }
            }
        }
        __syncthreads();
        if (i + 2 < nt) LOAD_STAGE(i & 1, (i + 2) << 5);
        asm volatile("cp.async.commit_group;");
    }
#undef LOAD_STAGE

    // epilogue
    const int g = lane >> 2, t = lane & 3;
#pragma unroll
    for (int a = 0; a < 4; a++) {
#pragma unroll
        for (int n = 0; n < 4; n++) {
            int row0 = bm + m0w + a * 16 + g;
            int col  = bn + n0w + n * 8 + 2 * t;
            float v0 = acc[a][n][0], v1 = acc[a][n][1];
            float v2 = acc[a][n][2], v3 = acc[a][n][3];
            if (BIAS) {
                float b0 = bias[col], b1 = bias[col + 1];
                v0 += b0; v1 += b1; v2 += b0; v3 += b1;
            }
            if (RELU) {
                v0 = fmaxf(v0, 0.f); v1 = fmaxf(v1, 0.f);
                v2 = fmaxf(v2, 0.f); v3 = fmaxf(v3, 0.f);
            }
            if (RES) {
                const float2 q0 = *(const float2*)(Res + (size_t)row0 * N + col);
                const float2 q1 = *(const float2*)(Res + (size_t)(row0 + 8) * N + col);
                v0 += q0.x; v1 += q0.y; v2 += q1.x; v3 += q1.y;
            }
            if (SPLITO) {
                __nv_bfloat162 h0, h1, l0, l1;
                split1(v0, h0.x, l0.x); split1(v1, h0.y, l0.y);
                split1(v2, h1.x, l1.x); split1(v3, h1.y, l1.y);
                *(__nv_bfloat162*)(OHi + (size_t)row0 * N + col)       = h0;
                *(__nv_bfloat162*)(OLo + (size_t)row0 * N + col)       = l0;
                *(__nv_bfloat162*)(OHi + (size_t)(row0 + 8) * N + col) = h1;
                *(__nv_bfloat162*)(OLo + (size_t)(row0 + 8) * N + col) = l1;
            } else {
                float2 o0; o0.x = v0; o0.y = v1;
                float2 o1; o1.x = v2; o1.y = v3;
                *(float2*)(C + (size_t)row0 * N + col)       = o0;
                *(float2*)(C + (size_t)(row0 + 8) * N + col) = o1;
            }
        }
    }
}

// ---------------------------------------------------------------------------
// QE[r, j] = sum_k Q[r,k] * pos_emb[k, j]  (pe rows stride 513: scalar loads)
// ---------------------------------------------------------------------------
__global__ __launch_bounds__(256) void qe_kernel(
    const float* __restrict__ QKVm, const float* __restrict__ pe,
    float* __restrict__ QE)
{
    __shared__ float Qs[64][64];
    __shared__ float Ps[64][68];
    const int rt = blockIdx.x;
    const int j0 = blockIdx.y * 64;
    const int tid = threadIdx.x;
    const int i  = tid >> 2;
    const int kb = (tid & 3) << 4;

    {
        int r = rt * 64 + i;
        int mrow = r >> 4, h = r & 15;
        const float* qp = QKVm + (size_t)mrow * QKV_N + h * 192 + kb;
#pragma unroll
        for (int q = 0; q < 4; q++)
            *(float4*)&Qs[i][kb + q * 4] = *(const float4*)(qp + q * 4);
    }
    {
        int k = i;
        const float* pp = pe + (size_t)k * NJ;
#pragma unroll
        for (int q = 0; q < 16; q++) {
            int jj = kb + q;
            int j = j0 + jj;
            Ps[k][jj] = (j <= 512) ? pp[j] : 0.f;
        }
    }
    __syncthreads();

    const int tx = tid & 15, ty = tid >> 4;
    float acc[4][4];
#pragma unroll
    for (int r = 0; r < 4; r++)
#pragma unroll
        for (int c = 0; c < 4; c++) acc[r][c] = 0.f;

#pragma unroll 4
    for (int k = 0; k < 64; k++) {
        float qv[4], pv[4];
#pragma unroll
        for (int r = 0; r < 4; r++) qv[r] = Qs[ty * 4 + r][k];
#pragma unroll
        for (int c = 0; c < 4; c++) pv[c] = Ps[k][tx * 4 + c];
#pragma unroll
        for (int r = 0; r < 4; r++)
#pragma unroll
            for (int c = 0; c < 4; c++)
                acc[r][c] += qv[r] * pv[c];
    }
#pragma unroll
    for (int r = 0; r < 4; r++) {
        size_t rowo = (size_t)(rt * 64 + ty * 4 + r) * NJ;
#pragma unroll
        for (int c = 0; c < 4; c++) {
            int j = j0 + tx * 4 + c;
            if (j <= 512) QE[rowo + j] = acc[r][c];
        }
    }
}

// ---------------------------------------------------------------------------
// Sliding-window attention (flash-style). Writes split bf16 output directly.
// ---------------------------------------------------------------------------
__global__ __launch_bounds__(256) void attn_kernel(
    const float* __restrict__ QKVm, const float* __restrict__ QE,
    __nv_bfloat16* __restrict__ OHi, __nv_bfloat16* __restrict__ OLo)
{
    __shared__ float Qs[64 * 64];
    __shared__ float KT[64 * 64];
    __shared__ float Vs[64 * 64];

    const int s0 = blockIdx.x * 64;
    const int g  = blockIdx.y;
    const int bh = blockIdx.z;
    const int b = bh >> 4, h = bh & 15;
    const int tid = threadIdx.x;
    const int tx = tid & 15, ty = tid >> 4;
    const int tbase = g * 512 + s0;
    const int base_key = tbase - 512;

    const int li = tid >> 2;
    const int kb = (tid & 3) << 4;

    {
        int t = tbase + li;
        const float* qp = QKVm + (size_t)(t * 2 + b) * QKV_N + h * 192 + kb;
#pragma unroll
        for (int q = 0; q < 4; q++)
            *(float4*)&Qs[li * 64 + kb + q * 4] = *(const float4*)(qp + q * 4);
    }

    float O[4][4];
    float mrow[4], lrow[4];
#pragma unroll
    for (int r = 0; r < 4; r++) {
        mrow[r] = -1e30f; lrow[r] = 0.f;
#pragma unroll
        for (int c = 0; c < 4; c++) O[r][c] = 0.f;
    }
    size_t qe_base[4];
#pragma unroll
    for (int r = 0; r < 4; r++) {
        int t = tbase + ty * 4 + r;
        qe_base[r] = ((size_t)(t * 2 + b) * 16 + h) * NJ;
    }

    for (int kt = 0; kt < 9; kt++) {
        __syncthreads();
        {
            int kk = li;
            int u = base_key + kt * 64 + kk;
            if (u >= 0) {
                const float* kp = QKVm + (size_t)(u * 2 + b) * QKV_N + h * 192 + 64 + kb;
#pragma unroll
                for (int q = 0; q < 4; q++) {
                    float4 k4 = *(const float4*)(kp + q * 4);
                    int kc = kb + q * 4;
                    KT[(kc + 0) * 64 + kk] = k4.x;
                    KT[(kc + 1) * 64 + kk] = k4.y;
                    KT[(kc + 2) * 64 + kk] = k4.z;
                    KT[(kc + 3) * 64 + kk] = k4.w;
                    *(float4*)&Vs[kk * 64 + kc] = *(const float4*)(kp + 64 + q * 4);
                }
            } else {
                float4 z = make_float4(0.f, 0.f, 0.f, 0.f);
#pragma unroll
                for (int q = 0; q < 4; q++) {
                    int kc = kb + q * 4;
                    KT[(kc + 0) * 64 + kk] = 0.f;
                    KT[(kc + 1) * 64 + kk] = 0.f;
                    KT[(kc + 2) * 64 + kk] = 0.f;
                    KT[(kc + 3) * 64 + kk] = 0.f;
                    *(float4*)&Vs[kk * 64 + kc] = z;
                }
            }
        }
        __syncthreads();

        float acc[4][4];
#pragma unroll
        for (int r = 0; r < 4; r++)
#pragma unroll
            for (int c = 0; c < 4; c++) acc[r][c] = 0.f;
#pragma unroll 4
        for (int k = 0; k < 64; k++) {
            float qv[4], kv[4];
#pragma unroll
            for (int r = 0; r < 4; r++) qv[r] = Qs[(ty * 4 + r) * 64 + k];
#pragma unroll
            for (int c = 0; c < 4; c++) kv[c] = KT[k * 64 + tx * 4 + c];
#pragma unroll
            for (int r = 0; r < 4; r++)
#pragma unroll
                for (int c = 0; c < 4; c++)
                    acc[r][c] += qv[r] * kv[c];
        }

#pragma unroll
        for (int r = 0; r < 4; r++) {
            int si = ty * 4 + r;
#pragma unroll
            for (int c = 0; c < 4; c++) {
                int kk = tx * 4 + c;
                int j = kt * 64 + kk - si;
                int u = base_key + kt * 64 + kk;
                if (j >= 0 && j <= 512 && u >= 0)
                    acc[r][c] = (acc[r][c] + QE[qe_base[r] + j]) * 0.125f;
                else
                    acc[r][c] = -1e30f;
            }
        }
        float mnew[4], corr[4];
#pragma unroll
        for (int r = 0; r < 4; r++) {
            float tm = fmaxf(fmaxf(acc[r][0], acc[r][1]), fmaxf(acc[r][2], acc[r][3]));
#pragma unroll
            for (int o = 1; o < 16; o <<= 1)
                tm = fmaxf(tm, __shfl_xor_sync(0xffffffffu, tm, o));
            mnew[r] = fmaxf(mrow[r], tm);
            corr[r] = __expf(mrow[r] - mnew[r]);
            float rs = 0.f;
#pragma unroll
            for (int c = 0; c < 4; c++) {
                float p = (acc[r][c] > -5e29f) ? __expf(acc[r][c] - mnew[r]) : 0.f;
                acc[r][c] = p;
                rs += p;
            }
#pragma unroll
            for (int o = 1; o < 16; o <<= 1)
                rs += __shfl_xor_sync(0xffffffffu, rs, o);
            lrow[r] = lrow[r] * corr[r] + rs;
            mrow[r] = mnew[r];
#pragma unroll
            for (int c = 0; c < 4; c++) O[r][c] *= corr[r];
        }

        __syncthreads();
#pragma unroll
        for (int r = 0; r < 4; r++)
#pragma unroll
            for (int c = 0; c < 4; c++)
                KT[(ty * 4 + r) * 64 + tx * 4 + c] = acc[r][c];
        __syncthreads();

#pragma unroll 4
        for (int kk = 0; kk < 64; kk++) {
            float pv[4], vv[4];
#pragma unroll
            for (int r = 0; r < 4; r++) pv[r] = KT[(ty * 4 + r) * 64 + kk];
#pragma unroll
            for (int c = 0; c < 4; c++) vv[c] = Vs[kk * 64 + tx * 4 + c];
#pragma unroll
            for (int r = 0; r < 4; r++)
#pragma unroll
                for (int c = 0; c < 4; c++)
                    O[r][c] += pv[r] * vv[c];
        }
    }

#pragma unroll
    for (int r = 0; r < 4; r++) {
        int t = tbase + ty * 4 + r;
        float inv = 1.f / lrow[r];
        size_t base = (size_t)(t * 2 + b) * 1024 + h * 64 + tx * 4;
        __nv_bfloat162 h0, h1, l0, l1;
        split1(O[r][0] * inv, h0.x, l0.x);
        split1(O[r][1] * inv, h0.y, l0.y);
        split1(O[r][2] * inv, h1.x, l1.x);
        split1(O[r][3] * inv, h1.y, l1.y);
        *(__nv_bfloat162*)(OHi + base)     = h0;
        *(__nv_bfloat162*)(OHi + base + 2) = h1;
        *(__nv_bfloat162*)(OLo + base)     = l0;
        *(__nv_bfloat162*)(OLo + base + 2) = l1;
    }
}

// ---------------------------------------------------------------------------
// nxt output copy
// ---------------------------------------------------------------------------
__global__ __launch_bounds__(256) void nxt_kernel(
    const float* __restrict__ QKVm, float* __restrict__ NXT)
{
    int idx = blockIdx.x * 256 + threadIdx.x;
    int c  = idx & 127;
    int bh = (idx >> 7) & 31;
    int s  = idx >> 12;
    int b = bh >> 4, h = bh & 15;
    int t = 3584 + s;
    NXT[idx] = QKVm[(size_t)(t * 2 + b) * QKV_N + h * 192 + 64 + c];
}

// ---------------------------------------------------------------------------
extern "C" void kernel_launch(void* const* d_in, const int* in_sizes, int n_in,
                              void* d_out, int out_size)
{
    const float* x      = (const float*)d_in[0];
    const float* ln1_g  = (const float*)d_in[1];
    const float* ln1_b  = (const float*)d_in[2];
    const float* qkv_w  = (const float*)d_in[3];
    const float* qkv_b  = (const float*)d_in[4];
    const float* pos_emb= (const float*)d_in[5];
    const float* out_w  = (const float*)d_in[6];
    const float* ln2_g  = (const float*)d_in[7];
    const float* ln2_b  = (const float*)d_in[8];
    const float* fc1_w  = (const float*)d_in[9];
    const float* fc1_b  = (const float*)d_in[10];
    const float* fc2_w  = (const float*)d_in[11];
    const float* fc2_b  = (const float*)d_in[12];
    float* out = (float*)d_out;

    float* scratch = 0;
    cudaGetSymbolAddress((void**)&scratch, g_scratch);
    __nv_bfloat16 *Ahi, *Alo, *A2hi, *A2lo, *Whi, *Wlo;
    cudaGetSymbolAddress((void**)&Ahi, g_act_hi);
    cudaGetSymbolAddress((void**)&Alo, g_act_lo);
    cudaGetSymbolAddress((void**)&A2hi, g_act2_hi);
    cudaGetSymbolAddress((void**)&A2lo, g_act2_lo);
    cudaGetSymbolAddress((void**)&Whi, g_w_hi);
    cudaGetSymbolAddress((void**)&Wlo, g_w_lo);

    float* OUT1 = scratch + OFF_OUT1;
    float* QKVm = scratch + OFF_QKV;
    float* QE   = scratch + OFF_QE;

    cudaFuncSetAttribute(mma_gemm<true, false, false, false>, cudaFuncAttributeMaxDynamicSharedMemorySize, MMA_SMEM);
    cudaFuncSetAttribute(mma_gemm<false, false, true, false>, cudaFuncAttributeMaxDynamicSharedMemorySize, MMA_SMEM);
    cudaFuncSetAttribute(mma_gemm<true, true, false, true>,   cudaFuncAttributeMaxDynamicSharedMemorySize, MMA_SMEM);
    cudaFuncSetAttribute(mma_gemm<true, false, true, false>,  cudaFuncAttributeMaxDynamicSharedMemorySize, MMA_SMEM);

    // 1. LN1 + split -> act
    ln_split_kernel<<<NROWS, 256>>>(x, ln1_g, ln1_b, Ahi, Alo);
    // 2. QKV = H @ qkv_w^T + qkv_b  (fp32 out)
    split_kernel<<<(QKV_N * EMB) / 1024, 256>>>(qkv_w, Whi, Wlo);
    mma_gemm<true, false, false, false><<<dim3(QKV_N / 128, NROWS / 128), 256, MMA_SMEM>>>(
        Ahi, Alo, Whi, Wlo, qkv_b, 0, QKVm, 0, 0, NROWS, QKV_N, EMB);
    // 3. QE = Q @ pos_emb
    qe_kernel<<<dim3(2048, 9), 256>>>(QKVm, pos_emb, QE);
    // 4. attention -> act (split out)
    attn_kernel<<<dim3(8, 8, 32), 256>>>(QKVm, QE, Ahi, Alo);
    // 5. OUT1 = AV @ out_w^T + x  (fp32: residual + LN2 input)
    split_kernel<<<(EMB * EMB) / 1024, 256>>>(out_w, Whi, Wlo);
    mma_gemm<false, false, true, false><<<dim3(EMB / 128, NROWS / 128), 256, MMA_SMEM>>>(
        Ahi, Alo, Whi, Wlo, 0, x, OUT1, 0, 0, NROWS, EMB, EMB);
    // 6. LN2 + split -> act
    ln_split_kernel<<<NROWS, 256>>>(OUT1, ln2_g, ln2_b, Ahi, Alo);
    // 7. act2 = split(relu(H2 @ fc1_w^T + fc1_b))
    split_kernel<<<(FFN_I * EMB) / 1024, 256>>>(fc1_w, Whi, Wlo);
    mma_gemm<true, true, false, true><<<dim3(FFN_I / 128, NROWS / 128), 256, MMA_SMEM>>>(
        Ahi, Alo, Whi, Wlo, fc1_b, 0, 0, A2hi, A2lo, NROWS, FFN_I, EMB);
    // 8. out = FF1 @ fc2_w^T + fc2_b + OUT1
    split_kernel<<<(EMB * FFN_I) / 1024, 256>>>(fc2_w, Whi, Wlo);
    mma_gemm<true, false, true, false><<<dim3(EMB / 128, NROWS / 128), 256, MMA_SMEM>>>(
        A2hi, A2lo, Whi, Wlo, fc2_b, OUT1, out, 0, 0, NROWS, EMB, FFN_I);
    // 9. nxt slice
    nxt_kernel<<<2097152 / 256, 256>>>(QKVm, out + 8388608);
}

// round 7
// speedup vs baseline: 1.9980x; 1.0416x over previous
#include <cuda_runtime.h>
#include <cuda_bf16.h>
#include <math.h>
#include <stdint.h>

// ---------------------------------------------------------------------------
// Shapes: x (T=4096, B=2, E=1024); H=16 heads, dk=dv=64; window 512 (513 rel pos)
// QKV rows = t*B + b (8192), cols = h*192 + c  (c<64 q, 64..127 k, 128..191 v)
// ---------------------------------------------------------------------------
#define NROWS 8192
#define EMB   1024
#define QKV_N 3072
#define FFN_I 4096
#define NJ    513

// fp32 scratch offsets (floats)
#define OFF_OUT1   16777216ull
#define OFF_QKV    33554432ull
#define OFF_QE     92274688ull
#define SCRATCH_FLOATS 159514624ull

__device__ float g_scratch[SCRATCH_FLOATS];

// split-bf16 buffers
__device__ __nv_bfloat16 g_act_hi[8388608];
__device__ __nv_bfloat16 g_act_lo[8388608];
__device__ __nv_bfloat16 g_act2_hi[33554432];
__device__ __nv_bfloat16 g_act2_lo[33554432];
__device__ __nv_bfloat16 g_w_hi[4194304];
__device__ __nv_bfloat16 g_w_lo[4194304];

__device__ __forceinline__ uint32_t smem_u32(const void* p) {
    uint32_t a;
    asm("{ .reg .u64 t; cvta.to.shared.u64 t, %1; cvt.u32.u64 %0, t; }" : "=r"(a) : "l"(p));
    return a;
}

__device__ __forceinline__ void split1(float v, __nv_bfloat16& h, __nv_bfloat16& l) {
    h = __float2bfloat16(v);
    l = __float2bfloat16(v - __bfloat162float(h));
}

// ---------------------------------------------------------------------------
// split fp32 -> (hi, lo) bf16   (weights)
// ---------------------------------------------------------------------------
__global__ __launch_bounds__(256) void split_kernel(
    const float* __restrict__ X, __nv_bfloat16* __restrict__ Hi,
    __nv_bfloat16* __restrict__ Lo)
{
    int i4 = blockIdx.x * 256 + threadIdx.x;
    float4 v = ((const float4*)X)[i4];
    __nv_bfloat162 hi0, hi1, lo0, lo1;
    split1(v.x, hi0.x, lo0.x);
    split1(v.y, hi0.y, lo0.y);
    split1(v.z, hi1.x, lo1.x);
    split1(v.w, hi1.y, lo1.y);
    ((__nv_bfloat162*)Hi)[i4 * 2]     = hi0;
    ((__nv_bfloat162*)Hi)[i4 * 2 + 1] = hi1;
    ((__nv_bfloat162*)Lo)[i4 * 2]     = lo0;
    ((__nv_bfloat162*)Lo)[i4 * 2 + 1] = lo1;
}

// ---------------------------------------------------------------------------
// LayerNorm fused with split
// ---------------------------------------------------------------------------
__global__ __launch_bounds__(256) void ln_split_kernel(
    const float* __restrict__ X, const float* __restrict__ G,
    const float* __restrict__ Bt, __nv_bfloat16* __restrict__ Hi,
    __nv_bfloat16* __restrict__ Lo)
{
    __shared__ float ssum[8], ssq[8], smv[2];
    int row = blockIdx.x;
    int tid = threadIdx.x;
    const float4* xr = (const float4*)(X + (size_t)row * EMB);
    float4 v = xr[tid];
    float s = v.x + v.y + v.z + v.w;
    float q = v.x*v.x + v.y*v.y + v.z*v.z + v.w*v.w;
#pragma unroll
    for (int o = 16; o > 0; o >>= 1) {
        s += __shfl_xor_sync(0xffffffffu, s, o);
        q += __shfl_xor_sync(0xffffffffu, q, o);
    }
    if ((tid & 31) == 0) { ssum[tid >> 5] = s; ssq[tid >> 5] = q; }
    __syncthreads();
    if (tid == 0) {
        float S = 0.f, Q = 0.f;
#pragma unroll
        for (int i = 0; i < 8; i++) { S += ssum[i]; Q += ssq[i]; }
        float mean = S * (1.f / EMB);
        float var  = Q * (1.f / EMB) - mean * mean;
        smv[0] = mean;
        smv[1] = rsqrtf(var + 1e-5f);
    }
    __syncthreads();
    float mean = smv[0], inv = smv[1];
    float4 g = ((const float4*)G)[tid];
    float4 b = ((const float4*)Bt)[tid];
    float o0 = (v.x - mean) * inv * g.x + b.x;
    float o1 = (v.y - mean) * inv * g.y + b.y;
    float o2 = (v.z - mean) * inv * g.z + b.z;
    float o3 = (v.w - mean) * inv * g.w + b.w;
    __nv_bfloat162 hi0, hi1, lo0, lo1;
    split1(o0, hi0.x, lo0.x);
    split1(o1, hi0.y, lo0.y);
    split1(o2, hi1.x, lo1.x);
    split1(o3, hi1.y, lo1.y);
    size_t i4 = (size_t)row * 256 + tid;
    ((__nv_bfloat162*)Hi)[i4 * 2]     = hi0;
    ((__nv_bfloat162*)Hi)[i4 * 2 + 1] = hi1;
    ((__nv_bfloat162*)Lo)[i4 * 2]     = lo0;
    ((__nv_bfloat162*)Lo)[i4 * 2 + 1] = lo1;
}

// ---------------------------------------------------------------------------
// mma.sync bf16 split GEMM NT (unchanged from r5 — proven)
// ---------------------------------------------------------------------------
#define STAGE_BYTES 32768
#define MMA_SMEM    65536

__device__ __forceinline__ void cp16(uint32_t dst, const void* src) {
    asm volatile("cp.async.cg.shared.global [%0], [%1], 16;" :: "r"(dst), "l"(src));
}
__device__ __forceinline__ void ldm4(uint32_t* r, uint32_t addr) {
    asm volatile("ldmatrix.sync.aligned.m8n8.x4.shared.b16 {%0,%1,%2,%3}, [%4];"
                 : "=r"(r[0]), "=r"(r[1]), "=r"(r[2]), "=r"(r[3]) : "r"(addr));
}
__device__ __forceinline__ void mma16816(float* c, const uint32_t* a,
                                         uint32_t b0, uint32_t b1) {
    asm volatile(
        "mma.sync.aligned.m16n8k16.row.col.f32.bf16.bf16.f32 "
        "{%0,%1,%2,%3}, {%4,%5,%6,%7}, {%8,%9}, {%0,%1,%2,%3};"
        : "+f"(c[0]), "+f"(c[1]), "+f"(c[2]), "+f"(c[3])
        : "r"(a[0]), "r"(a[1]), "r"(a[2]), "r"(a[3]), "r"(b0), "r"(b1));
}

template<bool BIAS, bool RELU, bool RES, bool SPLITO>
__global__ __launch_bounds__(256, 2) void mma_gemm(
    const __nv_bfloat16* __restrict__ Ah, const __nv_bfloat16* __restrict__ Al,
    const __nv_bfloat16* __restrict__ Bh, const __nv_bfloat16* __restrict__ Bl,
    const float* __restrict__ bias, const float* __restrict__ Res,
    float* __restrict__ C, __nv_bfloat16* __restrict__ OHi,
    __nv_bfloat16* __restrict__ OLo, int M, int N, int K)
{
    extern __shared__ char smem[];
    const uint32_t sbase = smem_u32(smem);
    const int tid = threadIdx.x;
    const int wid = tid >> 5, lane = tid & 31;
    const int bm = blockIdx.y * 128, bn = blockIdx.x * 128;
    const int m0w = (wid >> 2) * 64, n0w = (wid & 3) * 32;

    const int r0 = tid >> 2,         c0 = tid & 3;
    const int r1 = (tid + 256) >> 2, c1 = (tid + 256) & 3;
    const uint32_t so0 = (uint32_t)(r0 * 64 + ((c0 ^ ((r0 >> 1) & 3)) * 16));
    const uint32_t so1 = (uint32_t)(r1 * 64 + ((c1 ^ ((r1 >> 1) & 3)) * 16));
    const size_t offA0 = (size_t)(bm + r0) * K + c0 * 8;
    const size_t offA1 = (size_t)(bm + r1) * K + c1 * 8;
    const size_t offB0 = (size_t)(bn + r0) * K + c0 * 8;
    const size_t offB1 = (size_t)(bn + r1) * K + c1 * 8;

    float acc[4][4][4];
#pragma unroll
    for (int a = 0; a < 4; a++)
#pragma unroll
        for (int n = 0; n < 4; n++)
#pragma unroll
            for (int q = 0; q < 4; q++) acc[a][n][q] = 0.f;

    const int nt = K >> 5;
    const int rowA_base = m0w + (lane & 15);
    const int rowB_base = n0w + (lane & 15);
    const int chsel = lane >> 4;

#define LOAD_STAGE(s, k0)                                                     \
    do {                                                                      \
        uint32_t d = sbase + (s) * STAGE_BYTES;                               \
        cp16(d + so0,          Ah + offA0 + (k0));                            \
        cp16(d + so1,          Ah + offA1 + (k0));                            \
        cp16(d + 8192  + so0,  Al + offA0 + (k0));                            \
        cp16(d + 8192  + so1,  Al + offA1 + (k0));                            \
        cp16(d + 16384 + so0,  Bh + offB0 + (k0));                            \
        cp16(d + 16384 + so1,  Bh + offB1 + (k0));                            \
        cp16(d + 24576 + so0,  Bl + offB0 + (k0));                            \
        cp16(d + 24576 + so1,  Bl + offB1 + (k0));                            \
    } while (0)

    LOAD_STAGE(0, 0);
    asm volatile("cp.async.commit_group;");
    if (nt > 1) LOAD_STAGE(1, 32);
    asm volatile("cp.async.commit_group;");

    for (int i = 0; i < nt; i++) {
        asm volatile("cp.async.wait_group 1;");
        __syncthreads();
        uint32_t base = sbase + (i & 1) * STAGE_BYTES;
#pragma unroll
        for (int ks = 0; ks < 2; ks++) {
            const int chunk = ks * 2 + chsel;
            uint32_t bh[2][4], bl[2][4];
#pragma unroll
            for (int p = 0; p < 2; p++) {
                int row = rowB_base + p * 16;
                uint32_t ad = base + 16384 + (uint32_t)(row * 64 + ((chunk ^ ((row >> 1) & 3)) * 16));
                ldm4(bh[p], ad);
                ldm4(bl[p], ad + 8192);
            }
#pragma unroll
            for (int a = 0; a < 4; a++) {
                uint32_t ah[4], al[4];
                int row = rowA_base + a * 16;
                uint32_t ad = base + (uint32_t)(row * 64 + ((chunk ^ ((row >> 1) & 3)) * 16));
                ldm4(ah, ad);
                ldm4(al, ad + 8192);
#pragma unroll
                for (int n = 0; n < 4; n++) {
                    int p = n >> 1, q = n & 1;
                    mma16816(acc[a][n], ah, bh[p][q], bh[p][q + 2]);
                    mma16816(acc[a][n], ah, bl[p][q], bl[p][q + 2]);
                    mma16816(acc[a][n], al, bh[p][q], bh[p][q + 2]);
                }
            }
        }
        __syncthreads();
        if (i + 2 < nt) LOAD_STAGE(i & 1, (i + 2) << 5);
        asm volatile("cp.async.commit_group;");
    }
#undef LOAD_STAGE

    const int g = lane >> 2, t = lane & 3;
#pragma unroll
    for (int a = 0; a < 4; a++) {
#pragma unroll
        for (int n = 0; n < 4; n++) {
            int row0 = bm + m0w + a * 16 + g;
            int col  = bn + n0w + n * 8 + 2 * t;
            float v0 = acc[a][n][0], v1 = acc[a][n][1];
            float v2 = acc[a][n][2], v3 = acc[a][n][3];
            if (BIAS) {
                float b0 = bias[col], b1 = bias[col + 1];
                v0 += b0; v1 += b1; v2 += b0; v3 += b1;
            }
            if (RELU) {
                v0 = fmaxf(v0, 0.f); v1 = fmaxf(v1, 0.f);
                v2 = fmaxf(v2, 0.f); v3 = fmaxf(v3, 0.f);
            }
            if (RES) {
                const float2 q0 = *(const float2*)(Res + (size_t)row0 * N + col);
                const float2 q1 = *(const float2*)(Res + (size_t)(row0 + 8) * N + col);
                v0 += q0.x; v1 += q0.y; v2 += q1.x; v3 += q1.y;
            }
            if (SPLITO) {
                __nv_bfloat162 h0, h1, l0, l1;
                split1(v0, h0.x, l0.x); split1(v1, h0.y, l0.y);
                split1(v2, h1.x, l1.x); split1(v3, h1.y, l1.y);
                *(__nv_bfloat162*)(OHi + (size_t)row0 * N + col)       = h0;
                *(__nv_bfloat162*)(OLo + (size_t)row0 * N + col)       = l0;
                *(__nv_bfloat162*)(OHi + (size_t)(row0 + 8) * N + col) = h1;
                *(__nv_bfloat162*)(OLo + (size_t)(row0 + 8) * N + col) = l1;
            } else {
                float2 o0; o0.x = v0; o0.y = v1;
                float2 o1; o1.x = v2; o1.y = v3;
                *(float2*)(C + (size_t)row0 * N + col)       = o0;
                *(float2*)(C + (size_t)(row0 + 8) * N + col) = o1;
            }
        }
    }
}

// ---------------------------------------------------------------------------
// QE[r, j] = sum_k Q[r,k] * pos_emb[k, j].  Vectorized smem: Q stored
// transposed (QsT[k][i], stride 68) -> inner loop = 1 bcast LDS.128 + 1 LDS.128
// ---------------------------------------------------------------------------
__global__ __launch_bounds__(256) void qe_kernel(
    const float* __restrict__ QKVm, const float* __restrict__ pe,
    float* __restrict__ QE)
{
    __shared__ float QsT[64][68];   // [k][i]
    __shared__ float Ps[64][68];    // [k][jj]
    const int rt = blockIdx.x;
    const int j0 = blockIdx.y * 64;
    const int tid = threadIdx.x;
    const int i  = tid >> 2;
    const int kb = (tid & 3) << 4;

    {   // Q tile transposed: QsT[k][i]
        int r = rt * 64 + i;
        int mrow = r >> 4, h = r & 15;
        const float* qp = QKVm + (size_t)mrow * QKV_N + h * 192 + kb;
#pragma unroll
        for (int q = 0; q < 4; q++) {
            float4 v = *(const float4*)(qp + q * 4);
            QsT[kb + q * 4 + 0][i] = v.x;
            QsT[kb + q * 4 + 1][i] = v.y;
            QsT[kb + q * 4 + 2][i] = v.z;
            QsT[kb + q * 4 + 3][i] = v.w;
        }
    }
    {   // pos_emb tile (stride-513 rows: scalar loads)
        int k = i;
        const float* pp = pe + (size_t)k * NJ;
#pragma unroll
        for (int q = 0; q < 16; q++) {
            int jj = kb + q;
            int j = j0 + jj;
            Ps[k][jj] = (j <= 512) ? pp[j] : 0.f;
        }
    }
    __syncthreads();

    const int tx = tid & 15, ty = tid >> 4;
    float acc[4][4];
#pragma unroll
    for (int r = 0; r < 4; r++)
#pragma unroll
        for (int c = 0; c < 4; c++) acc[r][c] = 0.f;

#pragma unroll 8
    for (int k = 0; k < 64; k++) {
        float4 qv = *(const float4*)&QsT[k][ty * 4];
        float4 pv = *(const float4*)&Ps[k][tx * 4];
        float qa[4] = {qv.x, qv.y, qv.z, qv.w};
        float pa[4] = {pv.x, pv.y, pv.z, pv.w};
#pragma unroll
        for (int r = 0; r < 4; r++)
#pragma unroll
            for (int c = 0; c < 4; c++)
                acc[r][c] += qa[r] * pa[c];
    }
#pragma unroll
    for (int r = 0; r < 4; r++) {
        size_t rowo = (size_t)(rt * 64 + ty * 4 + r) * NJ;
#pragma unroll
        for (int c = 0; c < 4; c++) {
            int j = j0 + tx * 4 + c;
            if (j <= 512) QE[rowo + j] = acc[r][c];
        }
    }
}

// ---------------------------------------------------------------------------
// Sliding-window attention. Vectorized smem (stride-68 tiles):
//   S-loop: qv bcast LDS.128 + kv LDS.128;  PV-loop: pv bcast scalars + vv LDS.128
// smem = 3 * 64*68*4 = 52224 B (dynamic).
// ---------------------------------------------------------------------------
#define ATT_SMEM 52224
__global__ __launch_bounds__(256) void attn_kernel(
    const float* __restrict__ QKVm, const float* __restrict__ QE,
    __nv_bfloat16* __restrict__ OHi, __nv_bfloat16* __restrict__ OLo)
{
    extern __shared__ float sm[];
    float* QsT = sm;              // [k][si]  stride 68
    float* KT  = sm + 4352;       // [k][kk]  stride 68 ; reused as P[si][kk]
    float* Vs  = sm + 8704;       // [kk][d]  stride 68

    const int s0 = blockIdx.x * 64;
    const int g  = blockIdx.y;
    const int bh = blockIdx.z;
    const int b = bh >> 4, h = bh & 15;
    const int tid = threadIdx.x;
    const int tx = tid & 15, ty = tid >> 4;
    const int tbase = g * 512 + s0;
    const int base_key = tbase - 512;

    const int li = tid >> 2;
    const int kb = (tid & 3) << 4;

    {   // Q tile transposed
        int t = tbase + li;
        const float* qp = QKVm + (size_t)(t * 2 + b) * QKV_N + h * 192 + kb;
#pragma unroll
        for (int q = 0; q < 4; q++) {
            float4 v = *(const float4*)(qp + q * 4);
            QsT[(kb + q * 4 + 0) * 68 + li] = v.x;
            QsT[(kb + q * 4 + 1) * 68 + li] = v.y;
            QsT[(kb + q * 4 + 2) * 68 + li] = v.z;
            QsT[(kb + q * 4 + 3) * 68 + li] = v.w;
        }
    }

    float O[4][4];
    float mrow[4], lrow[4];
#pragma unroll
    for (int r = 0; r < 4; r++) {
        mrow[r] = -1e30f; lrow[r] = 0.f;
#pragma unroll
        for (int c = 0; c < 4; c++) O[r][c] = 0.f;
    }
    size_t qe_base[4];
#pragma unroll
    for (int r = 0; r < 4; r++) {
        int t = tbase + ty * 4 + r;
        qe_base[r] = ((size_t)(t * 2 + b) * 16 + h) * NJ;
    }

    for (int kt = 0; kt < 9; kt++) {
        __syncthreads();    // prior P reads done / Q store visible (kt==0)
        {   // K transposed + V tiles
            int kk = li;
            int u = base_key + kt * 64 + kk;
            if (u >= 0) {
                const float* kp = QKVm + (size_t)(u * 2 + b) * QKV_N + h * 192 + 64 + kb;
#pragma unroll
                for (int q = 0; q < 4; q++) {
                    float4 k4 = *(const float4*)(kp + q * 4);
                    int kc = kb + q * 4;
                    KT[(kc + 0) * 68 + kk] = k4.x;
                    KT[(kc + 1) * 68 + kk] = k4.y;
                    KT[(kc + 2) * 68 + kk] = k4.z;
                    KT[(kc + 3) * 68 + kk] = k4.w;
                    *(float4*)&Vs[kk * 68 + kc] = *(const float4*)(kp + 64 + q * 4);
                }
            } else {
                float4 z = make_float4(0.f, 0.f, 0.f, 0.f);
#pragma unroll
                for (int q = 0; q < 4; q++) {
                    int kc = kb + q * 4;
                    KT[(kc + 0) * 68 + kk] = 0.f;
                    KT[(kc + 1) * 68 + kk] = 0.f;
                    KT[(kc + 2) * 68 + kk] = 0.f;
                    KT[(kc + 3) * 68 + kk] = 0.f;
                    *(float4*)&Vs[kk * 68 + kc] = z;
                }
            }
        }
        __syncthreads();

        // S = Q.K^T   (2 x LDS.128 per k)
        float acc[4][4];
#pragma unroll
        for (int r = 0; r < 4; r++)
#pragma unroll
            for (int c = 0; c < 4; c++) acc[r][c] = 0.f;
#pragma unroll 8
        for (int k = 0; k < 64; k++) {
            float4 qv = *(const float4*)&QsT[k * 68 + ty * 4];
            float4 kv = *(const float4*)&KT[k * 68 + tx * 4];
            float qa[4] = {qv.x, qv.y, qv.z, qv.w};
            float ka[4] = {kv.x, kv.y, kv.z, kv.w};
#pragma unroll
            for (int r = 0; r < 4; r++)
#pragma unroll
                for (int c = 0; c < 4; c++)
                    acc[r][c] += qa[r] * ka[c];
        }

        // bias + mask + online softmax stats
#pragma unroll
        for (int r = 0; r < 4; r++) {
            int si = ty * 4 + r;
#pragma unroll
            for (int c = 0; c < 4; c++) {
                int kk = tx * 4 + c;
                int j = kt * 64 + kk - si;
                int u = base_key + kt * 64 + kk;
                if (j >= 0 && j <= 512 && u >= 0)
                    acc[r][c] = (acc[r][c] + QE[qe_base[r] + j]) * 0.125f;
                else
                    acc[r][c] = -1e30f;
            }
        }
        float mnew[4], corr[4];
#pragma unroll
        for (int r = 0; r < 4; r++) {
            float tm = fmaxf(fmaxf(acc[r][0], acc[r][1]), fmaxf(acc[r][2], acc[r][3]));
#pragma unroll
            for (int o = 1; o < 16; o <<= 1)
                tm = fmaxf(tm, __shfl_xor_sync(0xffffffffu, tm, o));
            mnew[r] = fmaxf(mrow[r], tm);
            corr[r] = __expf(mrow[r] - mnew[r]);
            float rs = 0.f;
#pragma unroll
            for (int c = 0; c < 4; c++) {
                float p = (acc[r][c] > -5e29f) ? __expf(acc[r][c] - mnew[r]) : 0.f;
                acc[r][c] = p;
                rs += p;
            }
#pragma unroll
            for (int o = 1; o < 16; o <<= 1)
                rs += __shfl_xor_sync(0xffffffffu, rs, o);
            lrow[r] = lrow[r] * corr[r] + rs;
            mrow[r] = mnew[r];
#pragma unroll
            for (int c = 0; c < 4; c++) O[r][c] *= corr[r];
        }

        __syncthreads();    // done reading KT as K
        // store P row-major (float4): P[si][kk]
#pragma unroll
        for (int r = 0; r < 4; r++) {
            float4 pv; pv.x = acc[r][0]; pv.y = acc[r][1];
            pv.z = acc[r][2]; pv.w = acc[r][3];
            *(float4*)&KT[(ty * 4 + r) * 68 + tx * 4] = pv;
        }
        __syncthreads();    // P visible

        // O += P.V   (4 bcast scalars + 1 LDS.128 per kk)
#pragma unroll 8
        for (int kk = 0; kk < 64; kk++) {
            float pa[4];
#pragma unroll
            for (int r = 0; r < 4; r++) pa[r] = KT[(ty * 4 + r) * 68 + kk];
            float4 vv = *(const float4*)&Vs[kk * 68 + tx * 4];
            float va[4] = {vv.x, vv.y, vv.z, vv.w};
#pragma unroll
            for (int r = 0; r < 4; r++)
#pragma unroll
                for (int c = 0; c < 4; c++)
                    O[r][c] += pa[r] * va[c];
        }
    }

#pragma unroll
    for (int r = 0; r < 4; r++) {
        int t = tbase + ty * 4 + r;
        float inv = 1.f / lrow[r];
        size_t base = (size_t)(t * 2 + b) * 1024 + h * 64 + tx * 4;
        __nv_bfloat162 h0, h1, l0, l1;
        split1(O[r][0] * inv, h0.x, l0.x);
        split1(O[r][1] * inv, h0.y, l0.y);
        split1(O[r][2] * inv, h1.x, l1.x);
        split1(O[r][3] * inv, h1.y, l1.y);
        *(__nv_bfloat162*)(OHi + base)     = h0;
        *(__nv_bfloat162*)(OHi + base + 2) = h1;
        *(__nv_bfloat162*)(OLo + base)     = l0;
        *(__nv_bfloat162*)(OLo + base + 2) = l1;
    }
}

// ---------------------------------------------------------------------------
// nxt output copy
// ---------------------------------------------------------------------------
__global__ __launch_bounds__(256) void nxt_kernel(
    const float* __restrict__ QKVm, float* __restrict__ NXT)
{
    int idx = blockIdx.x * 256 + threadIdx.x;
    int c  = idx & 127;
    int bh = (idx >> 7) & 31;
    int s  = idx >> 12;
    int b = bh >> 4, h = bh & 15;
    int t = 3584 + s;
    NXT[idx] = QKVm[(size_t)(t * 2 + b) * QKV_N + h * 192 + 64 + c];
}

// ---------------------------------------------------------------------------
extern "C" void kernel_launch(void* const* d_in, const int* in_sizes, int n_in,
                              void* d_out, int out_size)
{
    const float* x      = (const float*)d_in[0];
    const float* ln1_g  = (const float*)d_in[1];
    const float* ln1_b  = (const float*)d_in[2];
    const float* qkv_w  = (const float*)d_in[3];
    const float* qkv_b  = (const float*)d_in[4];
    const float* pos_emb= (const float*)d_in[5];
    const float* out_w  = (const float*)d_in[6];
    const float* ln2_g  = (const float*)d_in[7];
    const float* ln2_b  = (const float*)d_in[8];
    const float* fc1_w  = (const float*)d_in[9];
    const float* fc1_b  = (const float*)d_in[10];
    const float* fc2_w  = (const float*)d_in[11];
    const float* fc2_b  = (const float*)d_in[12];
    float* out = (float*)d_out;

    float* scratch = 0;
    cudaGetSymbolAddress((void**)&scratch, g_scratch);
    __nv_bfloat16 *Ahi, *Alo, *A2hi, *A2lo, *Whi, *Wlo;
    cudaGetSymbolAddress((void**)&Ahi, g_act_hi);
    cudaGetSymbolAddress((void**)&Alo, g_act_lo);
    cudaGetSymbolAddress((void**)&A2hi, g_act2_hi);
    cudaGetSymbolAddress((void**)&A2lo, g_act2_lo);
    cudaGetSymbolAddress((void**)&Whi, g_w_hi);
    cudaGetSymbolAddress((void**)&Wlo, g_w_lo);

    float* OUT1 = scratch + OFF_OUT1;
    float* QKVm = scratch + OFF_QKV;
    float* QE   = scratch + OFF_QE;

    cudaFuncSetAttribute(mma_gemm<true, false, false, false>, cudaFuncAttributeMaxDynamicSharedMemorySize, MMA_SMEM);
    cudaFuncSetAttribute(mma_gemm<false, false, true, false>, cudaFuncAttributeMaxDynamicSharedMemorySize, MMA_SMEM);
    cudaFuncSetAttribute(mma_gemm<true, true, false, true>,   cudaFuncAttributeMaxDynamicSharedMemorySize, MMA_SMEM);
    cudaFuncSetAttribute(mma_gemm<true, false, true, false>,  cudaFuncAttributeMaxDynamicSharedMemorySize, MMA_SMEM);
    cudaFuncSetAttribute(attn_kernel, cudaFuncAttributeMaxDynamicSharedMemorySize, ATT_SMEM);

    // 1. LN1 + split -> act
    ln_split_kernel<<<NROWS, 256>>>(x, ln1_g, ln1_b, Ahi, Alo);
    // 2. QKV = H @ qkv_w^T + qkv_b  (fp32 out)
    split_kernel<<<(QKV_N * EMB) / 1024, 256>>>(qkv_w, Whi, Wlo);
    mma_gemm<true, false, false, false><<<dim3(QKV_N / 128, NROWS / 128), 256, MMA_SMEM>>>(
        Ahi, Alo, Whi, Wlo, qkv_b, 0, QKVm, 0, 0, NROWS, QKV_N, EMB);
    // 3. QE = Q @ pos_emb
    qe_kernel<<<dim3(2048, 9), 256>>>(QKVm, pos_emb, QE);
    // 4. attention -> act (split out)
    attn_kernel<<<dim3(8, 8, 32), 256, ATT_SMEM>>>(QKVm, QE, Ahi, Alo);
    // 5. OUT1 = AV @ out_w^T + x
    split_kernel<<<(EMB * EMB) / 1024, 256>>>(out_w, Whi, Wlo);
    mma_gemm<false, false, true, false><<<dim3(EMB / 128, NROWS / 128), 256, MMA_SMEM>>>(
        Ahi, Alo, Whi, Wlo, 0, x, OUT1, 0, 0, NROWS, EMB, EMB);
    // 6. LN2 + split -> act
    ln_split_kernel<<<NROWS, 256>>>(OUT1, ln2_g, ln2_b, Ahi, Alo);
    // 7. act2 = split(relu(H2 @ fc1_w^T + fc1_b))
    split_kernel<<<(FFN_I * EMB) / 1024, 256>>>(fc1_w, Whi, Wlo);
    mma_gemm<true, true, false, true><<<dim3(FFN_I / 128, NROWS / 128), 256, MMA_SMEM>>>(
        Ahi, Alo, Whi, Wlo, fc1_b, 0, 0, A2hi, A2lo, NROWS, FFN_I, EMB);
    // 8. out = FF1 @ fc2_w^T + fc2_b + OUT1
    split_kernel<<<(EMB * FFN_I) / 1024, 256>>>(fc2_w, Whi, Wlo);
    mma_gemm<true, false, true, false><<<dim3(EMB / 128, NROWS / 128), 256, MMA_SMEM>>>(
        A2hi, A2lo, Whi, Wlo, fc2_b, OUT1, out, 0, 0, NROWS, EMB, FFN_I);
    // 9. nxt slice
    nxt_kernel<<<2097152 / 256, 256>>>(QKVm, out + 8388608);
}

// round 8
// speedup vs baseline: 2.1640x; 1.0831x over previous
#include <cuda_runtime.h>
#include <cuda_bf16.h>
#include <math.h>
#include <stdint.h>

// ---------------------------------------------------------------------------
// Shapes: x (T=4096, B=2, E=1024); H=16 heads, dk=dv=64; window 512 (513 rel pos)
// QKV rows = t*B + b (8192), cols = h*192 + c  (c<64 q, 64..127 k, 128..191 v)
// QE layout: [r = (t*2+b)*16+h][j], row stride 640 (cols 513..639 are pad)
// ---------------------------------------------------------------------------
#define NROWS 8192
#define EMB   1024
#define QKV_N 3072
#define FFN_I 4096
#define NJ    513
#define NJP   640

// fp32 scratch offsets (floats)
#define OFF_OUT1   16777216ull
#define OFF_QKV    33554432ull
#define OFF_QE     92274688ull   // 131072*640 = 83886080 -> ends 176160768
#define SCRATCH_FLOATS 176160768ull

__device__ float g_scratch[SCRATCH_FLOATS];

// split-bf16 buffers
__device__ __nv_bfloat16 g_act_hi[8388608];
__device__ __nv_bfloat16 g_act_lo[8388608];
__device__ __nv_bfloat16 g_act2_hi[33554432];   // fc1 out; reused as Qsplit earlier
__device__ __nv_bfloat16 g_act2_lo[33554432];
__device__ __nv_bfloat16 g_w_hi[4194304];
__device__ __nv_bfloat16 g_w_lo[4194304];
__device__ __nv_bfloat16 g_pet_hi[40960];       // pe^T padded [640][64]
__device__ __nv_bfloat16 g_pet_lo[40960];

__device__ __forceinline__ uint32_t smem_u32(const void* p) {
    uint32_t a;
    asm("{ .reg .u64 t; cvta.to.shared.u64 t, %1; cvt.u32.u64 %0, t; }" : "=r"(a) : "l"(p));
    return a;
}

__device__ __forceinline__ void split1(float v, __nv_bfloat16& h, __nv_bfloat16& l) {
    h = __float2bfloat16(v);
    l = __float2bfloat16(v - __bfloat162float(h));
}

// ---------------------------------------------------------------------------
// split fp32 -> (hi, lo) bf16   (weights)
// ---------------------------------------------------------------------------
__global__ __launch_bounds__(256) void split_kernel(
    const float* __restrict__ X, __nv_bfloat16* __restrict__ Hi,
    __nv_bfloat16* __restrict__ Lo)
{
    int i4 = blockIdx.x * 256 + threadIdx.x;
    float4 v = ((const float4*)X)[i4];
    __nv_bfloat162 hi0, hi1, lo0, lo1;
    split1(v.x, hi0.x, lo0.x);
    split1(v.y, hi0.y, lo0.y);
    split1(v.z, hi1.x, lo1.x);
    split1(v.w, hi1.y, lo1.y);
    ((__nv_bfloat162*)Hi)[i4 * 2]     = hi0;
    ((__nv_bfloat162*)Hi)[i4 * 2 + 1] = hi1;
    ((__nv_bfloat162*)Lo)[i4 * 2]     = lo0;
    ((__nv_bfloat162*)Lo)[i4 * 2 + 1] = lo1;
}

// ---------------------------------------------------------------------------
// pe^T split: out[j][k] = split(pe[k*513 + j]), j<513 else 0.  640*64 elems.
// ---------------------------------------------------------------------------
__global__ __launch_bounds__(256) void pe_split_t_kernel(
    const float* __restrict__ pe, __nv_bfloat16* __restrict__ Hi,
    __nv_bfloat16* __restrict__ Lo)
{
    int idx = blockIdx.x * 256 + threadIdx.x;   // 40960
    int k = idx & 63;
    int j = idx >> 6;
    float v = (j < NJ) ? pe[(size_t)k * NJ + j] : 0.f;
    __nv_bfloat16 h, l;
    split1(v, h, l);
    Hi[idx] = h;
    Lo[idx] = l;
}

// ---------------------------------------------------------------------------
// LayerNorm fused with split
// ---------------------------------------------------------------------------
__global__ __launch_bounds__(256) void ln_split_kernel(
    const float* __restrict__ X, const float* __restrict__ G,
    const float* __restrict__ Bt, __nv_bfloat16* __restrict__ Hi,
    __nv_bfloat16* __restrict__ Lo)
{
    __shared__ float ssum[8], ssq[8], smv[2];
    int row = blockIdx.x;
    int tid = threadIdx.x;
    const float4* xr = (const float4*)(X + (size_t)row * EMB);
    float4 v = xr[tid];
    float s = v.x + v.y + v.z + v.w;
    float q = v.x*v.x + v.y*v.y + v.z*v.z + v.w*v.w;
#pragma unroll
    for (int o = 16; o > 0; o >>= 1) {
        s += __shfl_xor_sync(0xffffffffu, s, o);
        q += __shfl_xor_sync(0xffffffffu, q, o);
    }
    if ((tid & 31) == 0) { ssum[tid >> 5] = s; ssq[tid >> 5] = q; }
    __syncthreads();
    if (tid == 0) {
        float S = 0.f, Q = 0.f;
#pragma unroll
        for (int i = 0; i < 8; i++) { S += ssum[i]; Q += ssq[i]; }
        float mean = S * (1.f / EMB);
        float var  = Q * (1.f / EMB) - mean * mean;
        smv[0] = mean;
        smv[1] = rsqrtf(var + 1e-5f);
    }
    __syncthreads();
    float mean = smv[0], inv = smv[1];
    float4 g = ((const float4*)G)[tid];
    float4 b = ((const float4*)Bt)[tid];
    float o0 = (v.x - mean) * inv * g.x + b.x;
    float o1 = (v.y - mean) * inv * g.y + b.y;
    float o2 = (v.z - mean) * inv * g.z + b.z;
    float o3 = (v.w - mean) * inv * g.w + b.w;
    __nv_bfloat162 hi0, hi1, lo0, lo1;
    split1(o0, hi0.x, lo0.x);
    split1(o1, hi0.y, lo0.y);
    split1(o2, hi1.x, lo1.x);
    split1(o3, hi1.y, lo1.y);
    size_t i4 = (size_t)row * 256 + tid;
    ((__nv_bfloat162*)Hi)[i4 * 2]     = hi0;
    ((__nv_bfloat162*)Hi)[i4 * 2 + 1] = hi1;
    ((__nv_bfloat162*)Lo)[i4 * 2]     = lo0;
    ((__nv_bfloat162*)Lo)[i4 * 2 + 1] = lo1;
}

// ---------------------------------------------------------------------------
// mma.sync bf16 split GEMM NT: C = (Ah+Al)(Bh+Bl)^T (+bias)(relu)(+Res)
// CTA 128x128, BK=32, 8 warps, cp.async double buffer.
// SPLITO: write (hi,lo) bf16 instead of fp32.
// QOUT: also write q-columns (c%192<64) as split bf16 [row*16+h][64] (QKV only)
// ---------------------------------------------------------------------------
#define STAGE_BYTES 32768
#define MMA_SMEM    65536

__device__ __forceinline__ void cp16(uint32_t dst, const void* src) {
    asm volatile("cp.async.cg.shared.global [%0], [%1], 16;" :: "r"(dst), "l"(src));
}
__device__ __forceinline__ void ldm4(uint32_t* r, uint32_t addr) {
    asm volatile("ldmatrix.sync.aligned.m8n8.x4.shared.b16 {%0,%1,%2,%3}, [%4];"
                 : "=r"(r[0]), "=r"(r[1]), "=r"(r[2]), "=r"(r[3]) : "r"(addr));
}
__device__ __forceinline__ void mma16816(float* c, const uint32_t* a,
                                         uint32_t b0, uint32_t b1) {
    asm volatile(
        "mma.sync.aligned.m16n8k16.row.col.f32.bf16.bf16.f32 "
        "{%0,%1,%2,%3}, {%4,%5,%6,%7}, {%8,%9}, {%0,%1,%2,%3};"
        : "+f"(c[0]), "+f"(c[1]), "+f"(c[2]), "+f"(c[3])
        : "r"(a[0]), "r"(a[1]), "r"(a[2]), "r"(a[3]), "r"(b0), "r"(b1));
}

template<bool BIAS, bool RELU, bool RES, bool SPLITO, bool QOUT>
__global__ __launch_bounds__(256, 2) void mma_gemm(
    const __nv_bfloat16* __restrict__ Ah, const __nv_bfloat16* __restrict__ Al,
    const __nv_bfloat16* __restrict__ Bh, const __nv_bfloat16* __restrict__ Bl,
    const float* __restrict__ bias, const float* __restrict__ Res,
    float* __restrict__ C, __nv_bfloat16* __restrict__ OHi,
    __nv_bfloat16* __restrict__ OLo, int M, int N, int K)
{
    extern __shared__ char smem[];
    const uint32_t sbase = smem_u32(smem);
    const int tid = threadIdx.x;
    const int wid = tid >> 5, lane = tid & 31;
    const int bm = blockIdx.y * 128, bn = blockIdx.x * 128;
    const int m0w = (wid >> 2) * 64, n0w = (wid & 3) * 32;

    const int r0 = tid >> 2,         c0 = tid & 3;
    const int r1 = (tid + 256) >> 2, c1 = (tid + 256) & 3;
    const uint32_t so0 = (uint32_t)(r0 * 64 + ((c0 ^ ((r0 >> 1) & 3)) * 16));
    const uint32_t so1 = (uint32_t)(r1 * 64 + ((c1 ^ ((r1 >> 1) & 3)) * 16));
    const size_t offA0 = (size_t)(bm + r0) * K + c0 * 8;
    const size_t offA1 = (size_t)(bm + r1) * K + c1 * 8;
    const size_t offB0 = (size_t)(bn + r0) * K + c0 * 8;
    const size_t offB1 = (size_t)(bn + r1) * K + c1 * 8;

    float acc[4][4][4];
#pragma unroll
    for (int a = 0; a < 4; a++)
#pragma unroll
        for (int n = 0; n < 4; n++)
#pragma unroll
            for (int q = 0; q < 4; q++) acc[a][n][q] = 0.f;

    const int nt = K >> 5;
    const int rowA_base = m0w + (lane & 15);
    const int rowB_base = n0w + (lane & 15);
    const int chsel = lane >> 4;

#define LOAD_STAGE(s, k0)                                                     \
    do {                                                                      \
        uint32_t d = sbase + (s) * STAGE_BYTES;                               \
        cp16(d + so0,          Ah + offA0 + (k0));                            \
        cp16(d + so1,          Ah + offA1 + (k0));                            \
        cp16(d + 8192  + so0,  Al + offA0 + (k0));                            \
        cp16(d + 8192  + so1,  Al + offA1 + (k0));                            \
        cp16(d + 16384 + so0,  Bh + offB0 + (k0));                            \
        cp16(d + 16384 + so1,  Bh + offB1 + (k0));                            \
        cp16(d + 24576 + so0,  Bl + offB0 + (k0));                            \
        cp16(d + 24576 + so1,  Bl + offB1 + (k0));                            \
    } while (0)

    LOAD_STAGE(0, 0);
    asm volatile("cp.async.commit_group;");
    if (nt > 1) LOAD_STAGE(1, 32);
    asm volatile("cp.async.commit_group;");

    for (int i = 0; i < nt; i++) {
        asm volatile("cp.async.wait_group 1;");
        __syncthreads();
        uint32_t base = sbase + (i & 1) * STAGE_BYTES;
#pragma unroll
        for (int ks = 0; ks < 2; ks++) {
            const int chunk = ks * 2 + chsel;
            uint32_t bh[2][4], bl[2][4];
#pragma unroll
            for (int p = 0; p < 2; p++) {
                int row = rowB_base + p * 16;
                uint32_t ad = base + 16384 + (uint32_t)(row * 64 + ((chunk ^ ((row >> 1) & 3)) * 16));
                ldm4(bh[p], ad);
                ldm4(bl[p], ad + 8192);
            }
#pragma unroll
            for (int a = 0; a < 4; a++) {
                uint32_t ah[4], al[4];
                int row = rowA_base + a * 16;
                uint32_t ad = base + (uint32_t)(row * 64 + ((chunk ^ ((row >> 1) & 3)) * 16));
                ldm4(ah, ad);
                ldm4(al, ad + 8192);
#pragma unroll
                for (int n = 0; n < 4; n++) {
                    int p = n >> 1, q = n & 1;
                    mma16816(acc[a][n], ah, bh[p][q], bh[p][q + 2]);
                    mma16816(acc[a][n], ah, bl[p][q], bl[p][q + 2]);
                    mma16816(acc[a][n], al, bh[p][q], bh[p][q + 2]);
                }
            }
        }
        __syncthreads();
        if (i + 2 < nt) LOAD_STAGE(i & 1, (i + 2) << 5);
        asm volatile("cp.async.commit_group;");
    }
#undef LOAD_STAGE

    const int g = lane >> 2, t = lane & 3;
#pragma unroll
    for (int a = 0; a < 4; a++) {
#pragma unroll
        for (int n = 0; n < 4; n++) {
            int row0 = bm + m0w + a * 16 + g;
            int col  = bn + n0w + n * 8 + 2 * t;
            float v0 = acc[a][n][0], v1 = acc[a][n][1];
            float v2 = acc[a][n][2], v3 = acc[a][n][3];
            if (BIAS) {
                float b0 = bias[col], b1 = bias[col + 1];
                v0 += b0; v1 += b1; v2 += b0; v3 += b1;
            }
            if (RELU) {
                v0 = fmaxf(v0, 0.f); v1 = fmaxf(v1, 0.f);
                v2 = fmaxf(v2, 0.f); v3 = fmaxf(v3, 0.f);
            }
            if (RES) {
                const float2 q0 = *(const float2*)(Res + (size_t)row0 * N + col);
                const float2 q1 = *(const float2*)(Res + (size_t)(row0 + 8) * N + col);
                v0 += q0.x; v1 += q0.y; v2 += q1.x; v3 += q1.y;
            }
            if (SPLITO) {
                __nv_bfloat162 h0, h1, l0, l1;
                split1(v0, h0.x, l0.x); split1(v1, h0.y, l0.y);
                split1(v2, h1.x, l1.x); split1(v3, h1.y, l1.y);
                *(__nv_bfloat162*)(OHi + (size_t)row0 * N + col)       = h0;
                *(__nv_bfloat162*)(OLo + (size_t)row0 * N + col)       = l0;
                *(__nv_bfloat162*)(OHi + (size_t)(row0 + 8) * N + col) = h1;
                *(__nv_bfloat162*)(OLo + (size_t)(row0 + 8) * N + col) = l1;
            } else {
                float2 o0; o0.x = v0; o0.y = v1;
                float2 o1; o1.x = v2; o1.y = v3;
                *(float2*)(C + (size_t)row0 * N + col)       = o0;
                *(float2*)(C + (size_t)(row0 + 8) * N + col) = o1;
            }
            if (QOUT) {
                int hh = col / 192;
                int cc = col - hh * 192;
                if (cc < 64) {
                    size_t q0o = ((size_t)row0 * 16 + hh) * 64 + cc;
                    size_t q1o = ((size_t)(row0 + 8) * 16 + hh) * 64 + cc;
                    __nv_bfloat162 h0, h1, l0, l1;
                    split1(v0, h0.x, l0.x); split1(v1, h0.y, l0.y);
                    split1(v2, h1.x, l1.x); split1(v3, h1.y, l1.y);
                    *(__nv_bfloat162*)(OHi + q0o) = h0;
                    *(__nv_bfloat162*)(OLo + q0o) = l0;
                    *(__nv_bfloat162*)(OHi + q1o) = h1;
                    *(__nv_bfloat162*)(OLo + q1o) = l1;
                }
            }
        }
    }
}

// ---------------------------------------------------------------------------
// Sliding-window attention (r7 version; QE row stride now NJP)
// ---------------------------------------------------------------------------
#define ATT_SMEM 52224
__global__ __launch_bounds__(256) void attn_kernel(
    const float* __restrict__ QKVm, const float* __restrict__ QE,
    __nv_bfloat16* __restrict__ OHi, __nv_bfloat16* __restrict__ OLo)
{
    extern __shared__ float sm[];
    float* QsT = sm;              // [k][si]  stride 68
    float* KT  = sm + 4352;       // [k][kk]  stride 68 ; reused as P[si][kk]
    float* Vs  = sm + 8704;       // [kk][d]  stride 68

    const int s0 = blockIdx.x * 64;
    const int g  = blockIdx.y;
    const int bh = blockIdx.z;
    const int b = bh >> 4, h = bh & 15;
    const int tid = threadIdx.x;
    const int tx = tid & 15, ty = tid >> 4;
    const int tbase = g * 512 + s0;
    const int base_key = tbase - 512;

    const int li = tid >> 2;
    const int kb = (tid & 3) << 4;

    {
        int t = tbase + li;
        const float* qp = QKVm + (size_t)(t * 2 + b) * QKV_N + h * 192 + kb;
#pragma unroll
        for (int q = 0; q < 4; q++) {
            float4 v = *(const float4*)(qp + q * 4);
            QsT[(kb + q * 4 + 0) * 68 + li] = v.x;
            QsT[(kb + q * 4 + 1) * 68 + li] = v.y;
            QsT[(kb + q * 4 + 2) * 68 + li] = v.z;
            QsT[(kb + q * 4 + 3) * 68 + li] = v.w;
        }
    }

    float O[4][4];
    float mrow[4], lrow[4];
#pragma unroll
    for (int r = 0; r < 4; r++) {
        mrow[r] = -1e30f; lrow[r] = 0.f;
#pragma unroll
        for (int c = 0; c < 4; c++) O[r][c] = 0.f;
    }
    size_t qe_base[4];
#pragma unroll
    for (int r = 0; r < 4; r++) {
        int t = tbase + ty * 4 + r;
        qe_base[r] = ((size_t)(t * 2 + b) * 16 + h) * NJP;
    }

    for (int kt = 0; kt < 9; kt++) {
        __syncthreads();
        {
            int kk = li;
            int u = base_key + kt * 64 + kk;
            if (u >= 0) {
                const float* kp = QKVm + (size_t)(u * 2 + b) * QKV_N + h * 192 + 64 + kb;
#pragma unroll
                for (int q = 0; q < 4; q++) {
                    float4 k4 = *(const float4*)(kp + q * 4);
                    int kc = kb + q * 4;
                    KT[(kc + 0) * 68 + kk] = k4.x;
                    KT[(kc + 1) * 68 + kk] = k4.y;
                    KT[(kc + 2) * 68 + kk] = k4.z;
                    KT[(kc + 3) * 68 + kk] = k4.w;
                    *(float4*)&Vs[kk * 68 + kc] = *(const float4*)(kp + 64 + q * 4);
                }
            } else {
                float4 z = make_float4(0.f, 0.f, 0.f, 0.f);
#pragma unroll
                for (int q = 0; q < 4; q++) {
                    int kc = kb + q * 4;
                    KT[(kc + 0) * 68 + kk] = 0.f;
                    KT[(kc + 1) * 68 + kk] = 0.f;
                    KT[(kc + 2) * 68 + kk] = 0.f;
                    KT[(kc + 3) * 68 + kk] = 0.f;
                    *(float4*)&Vs[kk * 68 + kc] = z;
                }
            }
        }
        __syncthreads();

        float acc[4][4];
#pragma unroll
        for (int r = 0; r < 4; r++)
#pragma unroll
            for (int c = 0; c < 4; c++) acc[r][c] = 0.f;
#pragma unroll 8
        for (int k = 0; k < 64; k++) {
            float4 qv = *(const float4*)&QsT[k * 68 + ty * 4];
            float4 kv = *(const float4*)&KT[k * 68 + tx * 4];
            float qa[4] = {qv.x, qv.y, qv.z, qv.w};
            float ka[4] = {kv.x, kv.y, kv.z, kv.w};
#pragma unroll
            for (int r = 0; r < 4; r++)
#pragma unroll
                for (int c = 0; c < 4; c++)
                    acc[r][c] += qa[r] * ka[c];
        }

#pragma unroll
        for (int r = 0; r < 4; r++) {
            int si = ty * 4 + r;
#pragma unroll
            for (int c = 0; c < 4; c++) {
                int kk = tx * 4 + c;
                int j = kt * 64 + kk - si;
                int u = base_key + kt * 64 + kk;
                if (j >= 0 && j <= 512 && u >= 0)
                    acc[r][c] = (acc[r][c] + QE[qe_base[r] + j]) * 0.125f;
                else
                    acc[r][c] = -1e30f;
            }
        }
        float mnew[4], corr[4];
#pragma unroll
        for (int r = 0; r < 4; r++) {
            float tm = fmaxf(fmaxf(acc[r][0], acc[r][1]), fmaxf(acc[r][2], acc[r][3]));
#pragma unroll
            for (int o = 1; o < 16; o <<= 1)
                tm = fmaxf(tm, __shfl_xor_sync(0xffffffffu, tm, o));
            mnew[r] = fmaxf(mrow[r], tm);
            corr[r] = __expf(mrow[r] - mnew[r]);
            float rs = 0.f;
#pragma unroll
            for (int c = 0; c < 4; c++) {
                float p = (acc[r][c] > -5e29f) ? __expf(acc[r][c] - mnew[r]) : 0.f;
                acc[r][c] = p;
                rs += p;
            }
#pragma unroll
            for (int o = 1; o < 16; o <<= 1)
                rs += __shfl_xor_sync(0xffffffffu, rs, o);
            lrow[r] = lrow[r] * corr[r] + rs;
            mrow[r] = mnew[r];
#pragma unroll
            for (int c = 0; c < 4; c++) O[r][c] *= corr[r];
        }

        __syncthreads();
#pragma unroll
        for (int r = 0; r < 4; r++) {
            float4 pv; pv.x = acc[r][0]; pv.y = acc[r][1];
            pv.z = acc[r][2]; pv.w = acc[r][3];
            *(float4*)&KT[(ty * 4 + r) * 68 + tx * 4] = pv;
        }
        __syncthreads();

#pragma unroll 8
        for (int kk = 0; kk < 64; kk++) {
            float pa[4];
#pragma unroll
            for (int r = 0; r < 4; r++) pa[r] = KT[(ty * 4 + r) * 68 + kk];
            float4 vv = *(const float4*)&Vs[kk * 68 + tx * 4];
            float va[4] = {vv.x, vv.y, vv.z, vv.w};
#pragma unroll
            for (int r = 0; r < 4; r++)
#pragma unroll
                for (int c = 0; c < 4; c++)
                    O[r][c] += pa[r] * va[c];
        }
    }

#pragma unroll
    for (int r = 0; r < 4; r++) {
        int t = tbase + ty * 4 + r;
        float inv = 1.f / lrow[r];
        size_t base = (size_t)(t * 2 + b) * 1024 + h * 64 + tx * 4;
        __nv_bfloat162 h0, h1, l0, l1;
        split1(O[r][0] * inv, h0.x, l0.x);
        split1(O[r][1] * inv, h0.y, l0.y);
        split1(O[r][2] * inv, h1.x, l1.x);
        split1(O[r][3] * inv, h1.y, l1.y);
        *(__nv_bfloat162*)(OHi + base)     = h0;
        *(__nv_bfloat162*)(OHi + base + 2) = h1;
        *(__nv_bfloat162*)(OLo + base)     = l0;
        *(__nv_bfloat162*)(OLo + base + 2) = l1;
    }
}

// ---------------------------------------------------------------------------
// nxt output copy
// ---------------------------------------------------------------------------
__global__ __launch_bounds__(256) void nxt_kernel(
    const float* __restrict__ QKVm, float* __restrict__ NXT)
{
    int idx = blockIdx.x * 256 + threadIdx.x;
    int c  = idx & 127;
    int bh = (idx >> 7) & 31;
    int s  = idx >> 12;
    int b = bh >> 4, h = bh & 15;
    int t = 3584 + s;
    NXT[idx] = QKVm[(size_t)(t * 2 + b) * QKV_N + h * 192 + 64 + c];
}

// ---------------------------------------------------------------------------
extern "C" void kernel_launch(void* const* d_in, const int* in_sizes, int n_in,
                              void* d_out, int out_size)
{
    const float* x      = (const float*)d_in[0];
    const float* ln1_g  = (const float*)d_in[1];
    const float* ln1_b  = (const float*)d_in[2];
    const float* qkv_w  = (const float*)d_in[3];
    const float* qkv_b  = (const float*)d_in[4];
    const float* pos_emb= (const float*)d_in[5];
    const float* out_w  = (const float*)d_in[6];
    const float* ln2_g  = (const float*)d_in[7];
    const float* ln2_b  = (const float*)d_in[8];
    const float* fc1_w  = (const float*)d_in[9];
    const float* fc1_b  = (const float*)d_in[10];
    const float* fc2_w  = (const float*)d_in[11];
    const float* fc2_b  = (const float*)d_in[12];
    float* out = (float*)d_out;

    float* scratch = 0;
    cudaGetSymbolAddress((void**)&scratch, g_scratch);
    __nv_bfloat16 *Ahi, *Alo, *A2hi, *A2lo, *Whi, *Wlo, *PThi, *PTlo;
    cudaGetSymbolAddress((void**)&Ahi, g_act_hi);
    cudaGetSymbolAddress((void**)&Alo, g_act_lo);
    cudaGetSymbolAddress((void**)&A2hi, g_act2_hi);
    cudaGetSymbolAddress((void**)&A2lo, g_act2_lo);
    cudaGetSymbolAddress((void**)&Whi, g_w_hi);
    cudaGetSymbolAddress((void**)&Wlo, g_w_lo);
    cudaGetSymbolAddress((void**)&PThi, g_pet_hi);
    cudaGetSymbolAddress((void**)&PTlo, g_pet_lo);

    float* OUT1 = scratch + OFF_OUT1;
    float* QKVm = scratch + OFF_QKV;
    float* QE   = scratch + OFF_QE;

    cudaFuncSetAttribute(mma_gemm<true, false, false, false, true>,  cudaFuncAttributeMaxDynamicSharedMemorySize, MMA_SMEM);
    cudaFuncSetAttribute(mma_gemm<false, false, false, false, false>,cudaFuncAttributeMaxDynamicSharedMemorySize, MMA_SMEM);
    cudaFuncSetAttribute(mma_gemm<false, false, true, false, false>, cudaFuncAttributeMaxDynamicSharedMemorySize, MMA_SMEM);
    cudaFuncSetAttribute(mma_gemm<true, true, false, true, false>,   cudaFuncAttributeMaxDynamicSharedMemorySize, MMA_SMEM);
    cudaFuncSetAttribute(mma_gemm<true, false, true, false, false>,  cudaFuncAttributeMaxDynamicSharedMemorySize, MMA_SMEM);
    cudaFuncSetAttribute(attn_kernel, cudaFuncAttributeMaxDynamicSharedMemorySize, ATT_SMEM);

    // 0. pe^T split (tiny, independent)
    pe_split_t_kernel<<<160, 256>>>(pos_emb, PThi, PTlo);
    // 1. LN1 + split -> act
    ln_split_kernel<<<NROWS, 256>>>(x, ln1_g, ln1_b, Ahi, Alo);
    // 2. QKV = H @ qkv_w^T + qkv_b (fp32), also emit Qsplit -> A2 buffers
    split_kernel<<<(QKV_N * EMB) / 1024, 256>>>(qkv_w, Whi, Wlo);
    mma_gemm<true, false, false, false, true><<<dim3(QKV_N / 128, NROWS / 128), 256, MMA_SMEM>>>(
        Ahi, Alo, Whi, Wlo, qkv_b, 0, QKVm, A2hi, A2lo, NROWS, QKV_N, EMB);
    // 3. QE = Qsplit @ peT^T  (M=131072, N=640, K=64)
    mma_gemm<false, false, false, false, false><<<dim3(NJP / 128, 131072 / 128), 256, MMA_SMEM>>>(
        A2hi, A2lo, PThi, PTlo, 0, 0, QE, 0, 0, 131072, NJP, 64);
    // 4. attention -> act (split out)
    attn_kernel<<<dim3(8, 8, 32), 256, ATT_SMEM>>>(QKVm, QE, Ahi, Alo);
    // 5. OUT1 = AV @ out_w^T + x
    split_kernel<<<(EMB * EMB) / 1024, 256>>>(out_w, Whi, Wlo);
    mma_gemm<false, false, true, false, false><<<dim3(EMB / 128, NROWS / 128), 256, MMA_SMEM>>>(
        Ahi, Alo, Whi, Wlo, 0, x, OUT1, 0, 0, NROWS, EMB, EMB);
    // 6. LN2 + split -> act
    ln_split_kernel<<<NROWS, 256>>>(OUT1, ln2_g, ln2_b, Ahi, Alo);
    // 7. act2 = split(relu(H2 @ fc1_w^T + fc1_b))
    split_kernel<<<(FFN_I * EMB) / 1024, 256>>>(fc1_w, Whi, Wlo);
    mma_gemm<true, true, false, true, false><<<dim3(FFN_I / 128, NROWS / 128), 256, MMA_SMEM>>>(
        Ahi, Alo, Whi, Wlo, fc1_b, 0, 0, A2hi, A2lo, NROWS, FFN_I, EMB);
    // 8. out = FF1 @ fc2_w^T + fc2_b + OUT1
    split_kernel<<<(EMB * FFN_I) / 1024, 256>>>(fc2_w, Whi, Wlo);
    mma_gemm<true, false, true, false, false><<<dim3(EMB / 128, NROWS / 128), 256, MMA_SMEM>>>(
        A2hi, A2lo, Whi, Wlo, fc2_b, OUT1, out, 0, 0, NROWS, EMB, FFN_I);
    // 9. nxt slice
    nxt_kernel<<<2097152 / 256, 256>>>(QKVm, out + 8388608);
}